// round 1
// baseline (speedup 1.0000x reference)
#include <cuda_runtime.h>
#include <math.h>

#define NN 5000
#define BB 8
#define TT 40000      // BB*NN
#define EE 40000
#define SS 12
#define FF 16
#define HH 128
#define LL 2
#define NE (EE + NN)  // CSR entries on the single graph (edges + self loops)

// ---------------- device scratch (static: no allocation allowed) ------------
__device__ float g_deg[NN];
__device__ float g_dis[NN];
__device__ int   g_cnt[NN];
__device__ int   g_ptr[NN + 1];
__device__ int   g_wpos[NN];
__device__ int   g_src[NE];
__device__ float g_wv[NE];
__device__ int   g_key[NE];

__device__ float g_Xt[(size_t)TT * HH];          // relu(lin_in) per step
__device__ float g_h[(size_t)LL * TT * HH];      // hidden states
__device__ float g_AXH[(size_t)TT * 2 * HH];     // [Ax | Ah] / [Ax | Arh]
__device__ float g_RH[(size_t)TT * HH];          // r * h
__device__ float g_U[(size_t)TT * HH];           // u gate
__device__ float g_Wru[(size_t)LL * 2 * HH * 2 * HH]; // packed [W_r | W_u]
__device__ float g_psum[160 * HH];
__device__ float g_psq[160 * HH];
__device__ float g_mean[HH];
__device__ float g_rstd[HH];

// ---------------- graph preprocessing ---------------------------------------
__global__ void k_prep_init() {
    int i = blockIdx.x * blockDim.x + threadIdx.x;
    if (i < NN) { g_deg[i] = 1.0f; g_cnt[i] = 1; }   // self-loop contributions
}

__global__ void k_prep_deg(const int* __restrict__ ei, const float* __restrict__ ew) {
    int e = blockIdx.x * blockDim.x + threadIdx.x;
    if (e < EE) {
        int c = ei[EE + e];
        atomicAdd(&g_deg[c], ew[e]);
        atomicAdd(&g_cnt[c], 1);
    }
}

__global__ void k_prep_dis() {
    int i = blockIdx.x * blockDim.x + threadIdx.x;
    if (i < NN) g_dis[i] = rsqrtf(g_deg[i]);
}

__global__ void k_scan() {
    __shared__ int sh[1024];
    __shared__ int carry;
    if (threadIdx.x == 0) carry = 0;
    __syncthreads();
    for (int base = 0; base < NN; base += 1024) {
        int i = base + threadIdx.x;
        int v = (i < NN) ? g_cnt[i] : 0;
        sh[threadIdx.x] = v;
        __syncthreads();
        for (int off = 1; off < 1024; off <<= 1) {
            int t = (threadIdx.x >= off) ? sh[threadIdx.x - off] : 0;
            __syncthreads();
            sh[threadIdx.x] += t;
            __syncthreads();
        }
        int excl = sh[threadIdx.x] - v + carry;
        if (i < NN) { g_ptr[i] = excl; }
        __syncthreads();
        if (threadIdx.x == 1023) carry += sh[1023];
        __syncthreads();
    }
    if (threadIdx.x == 0) g_ptr[NN] = carry;
}

__global__ void k_fill_self() {
    int i = blockIdx.x * blockDim.x + threadIdx.x;
    if (i < NN) {
        int p = g_ptr[i];
        g_src[p] = i;
        g_wv[p]  = g_dis[i] * g_dis[i];   // self-loop: dis[n]*1*dis[n]
        g_key[p] = -1;
        g_wpos[i] = p + 1;
    }
}

__global__ void k_fill_edges(const int* __restrict__ ei, const float* __restrict__ ew) {
    int e = blockIdx.x * blockDim.x + threadIdx.x;
    if (e < EE) {
        int r = ei[e];
        int c = ei[EE + e];
        int p = atomicAdd(&g_wpos[c], 1);
        g_src[p] = r;
        g_wv[p]  = g_dis[r] * ew[e] * g_dis[c];
        g_key[p] = e;
    }
}

__global__ void k_sort() {   // deterministic order: self loop first, edges by id
    int c = blockIdx.x * blockDim.x + threadIdx.x;
    if (c >= NN) return;
    int s0 = g_ptr[c] + 1, s1 = g_ptr[c + 1];
    for (int i = s0 + 1; i < s1; i++) {
        int k = g_key[i]; int sr = g_src[i]; float w = g_wv[i];
        int j = i - 1;
        while (j >= s0 && g_key[j] > k) {
            g_key[j + 1] = g_key[j]; g_src[j + 1] = g_src[j]; g_wv[j + 1] = g_wv[j];
            j--;
        }
        g_key[j + 1] = k; g_src[j + 1] = sr; g_wv[j + 1] = w;
    }
}

__global__ void pack_wru(const float* __restrict__ convW) {
    int i = blockIdx.x * blockDim.x + threadIdx.x;
    if (i < LL * 256 * 256) {
        int l = i / 65536, rem = i % 65536;
        int k = rem / 256, j2 = rem % 256;
        int g = j2 >> 7, j = j2 & 127;
        g_Wru[i] = convW[((size_t)(l * 3 + g) * 256 + k) * 128 + j];
    }
}

__global__ void zero_h() {
    size_t i = (size_t)blockIdx.x * blockDim.x + threadIdx.x;
    if (i < (size_t)LL * TT * HH) g_h[i] = 0.0f;
}

// ---------------- per-step kernels ------------------------------------------
__global__ void lin_in_kernel(const float* __restrict__ x_seq,
                              const float* __restrict__ W,
                              const float* __restrict__ bias, int s) {
    int t = blockIdx.x;                // node index in [0, TT)
    int b = t / NN, n = t - b * NN;
    int j = threadIdx.x;               // 0..127
    __shared__ float xs[FF];
    if (j < FF) xs[j] = x_seq[(((size_t)b * SS + s) * NN + n) * FF + j];
    __syncthreads();
    float acc = bias[j];
#pragma unroll
    for (int k = 0; k < FF; k++) acc = fmaf(xs[k], W[k * HH + j], acc);
    g_Xt[(size_t)t * HH + j] = fmaxf(acc, 0.0f);
}

// AXH[:, 0:128] = Ahat @ x_t ; AXH[:, 128:256] = Ahat @ h_l
__global__ void spmm_xh(int l) {
    int t = blockIdx.x;
    int c = t % NN;
    int base = t - c;                  // b*NN
    int j = threadIdx.x;               // 0..255
    const float* X = (l == 0) ? g_Xt : g_h;     // layer1 input = h0
    const float* src = (j < HH) ? X : (g_h + (size_t)l * TT * HH);
    int col = j & (HH - 1);
    int s0 = g_ptr[c], s1 = g_ptr[c + 1];
    float acc = 0.0f;
    for (int e = s0; e < s1; e++) {
        acc += g_wv[e] * src[(size_t)(base + g_src[e]) * HH + col];
    }
    g_AXH[(size_t)t * 256 + j] = acc;
}

// AXH[:, 128:256] = Ahat @ (r*h)
__global__ void spmm_rh() {
    int t = blockIdx.x;
    int c = t % NN;
    int base = t - c;
    int j = threadIdx.x;               // 0..127
    int s0 = g_ptr[c], s1 = g_ptr[c + 1];
    float acc = 0.0f;
    for (int e = s0; e < s1; e++) {
        acc += g_wv[e] * g_RH[(size_t)(base + g_src[e]) * HH + j];
    }
    g_AXH[(size_t)t * 256 + HH + j] = acc;
}

// ---------------- tiled SGEMM with fused GRU epilogues -----------------------
#define BM 128
#define BN 128
#define BK 16
#define TM 8
#define TN 8

// mode 0 (ru): C = AXH @ Wru[l]  -> blockIdx.y==0: RH = sigmoid(C+b_r)*h
//                                   blockIdx.y==1: U  = sigmoid(C+b_u)
// mode 1 (c) : C = AXH @ W2[l]   -> h = U*h + (1-U)*tanh(C+b_c)
__global__ void gemm_kernel(int mode, int l,
                            const float* __restrict__ convW,
                            const float* __restrict__ convB) {
    const float* A = g_AXH;
    const float* B;
    const float* bias;
    int ldb, ncol0;
    if (mode == 0) {
        B = g_Wru + (size_t)l * 256 * 256;
        ldb = 256;
        ncol0 = blockIdx.y * 128;
        bias = convB + l * 3 * HH + ncol0;
    } else {
        B = convW + (size_t)(l * 3 + 2) * 256 * 128;
        ldb = 128;
        ncol0 = 0;
        bias = convB + (l * 3 + 2) * HH;
    }

    __shared__ float As[BK][BM + 1];
    __shared__ float Bs[BK][BN];

    int tid = threadIdx.x;             // 256 threads
    int m0 = blockIdx.x * BM;
    int ty = tid >> 4, tx = tid & 15;

    float acc[TM][TN];
#pragma unroll
    for (int i = 0; i < TM; i++)
#pragma unroll
        for (int j = 0; j < TN; j++) acc[i][j] = 0.0f;

    for (int kt = 0; kt < 256; kt += BK) {
#pragma unroll
        for (int it = 0; it < 2; it++) {
            int idx = tid + it * 256;          // 0..511
            int row = idx >> 2;                // 0..127
            int k4  = (idx & 3) * 4;           // 0,4,8,12
            float4 v;
            int gr = m0 + row;
            if (gr < TT)
                v = *reinterpret_cast<const float4*>(&A[(size_t)gr * 256 + kt + k4]);
            else
                v = make_float4(0.f, 0.f, 0.f, 0.f);
            As[k4 + 0][row] = v.x; As[k4 + 1][row] = v.y;
            As[k4 + 2][row] = v.z; As[k4 + 3][row] = v.w;
        }
#pragma unroll
        for (int it = 0; it < 2; it++) {
            int idx = tid + it * 256;
            int k  = idx >> 5;                 // 0..15
            int n4 = (idx & 31) * 4;           // 0..124
            float4 v = *reinterpret_cast<const float4*>(&B[(size_t)(kt + k) * ldb + ncol0 + n4]);
            *reinterpret_cast<float4*>(&Bs[k][n4]) = v;
        }
        __syncthreads();
#pragma unroll
        for (int k = 0; k < BK; k++) {
            float ra[TM];
            float4 rb0 = *reinterpret_cast<const float4*>(&Bs[k][tx * TN]);
            float4 rb1 = *reinterpret_cast<const float4*>(&Bs[k][tx * TN + 4]);
            float rb[TN] = {rb0.x, rb0.y, rb0.z, rb0.w, rb1.x, rb1.y, rb1.z, rb1.w};
#pragma unroll
            for (int i = 0; i < TM; i++) ra[i] = As[k][ty * TM + i];
#pragma unroll
            for (int i = 0; i < TM; i++)
#pragma unroll
                for (int j = 0; j < TN; j++)
                    acc[i][j] = fmaf(ra[i], rb[j], acc[i][j]);
        }
        __syncthreads();
    }

    float* Hst = g_h + (size_t)l * TT * HH;
#pragma unroll
    for (int i = 0; i < TM; i++) {
        int m = m0 + ty * TM + i;
        if (m >= TT) continue;
#pragma unroll
        for (int j = 0; j < TN; j++) {
            int n = tx * TN + j;
            float v = acc[i][j] + bias[n];
            size_t o = (size_t)m * HH + n;
            if (mode == 0) {
                float sg = 1.0f / (1.0f + expf(-v));
                if (blockIdx.y == 0) g_RH[o] = sg * Hst[o];
                else                 g_U[o] = sg;
            } else {
                float cc = tanhf(v);
                float u  = g_U[o];
                Hst[o] = u * Hst[o] + (1.0f - u) * cc;
            }
        }
    }
}

// ---------------- batchnorm + output -----------------------------------------
__global__ void bn_partial() {     // grid 160, block 128
    int j = threadIdx.x;
    int b = blockIdx.x;
    const float* h1 = g_h + (size_t)(LL - 1) * TT * HH;
    float s = 0.0f, q = 0.0f;
    int r0 = b * (TT / 160), r1 = r0 + (TT / 160);
    for (int r = r0; r < r1; r++) {
        float v = h1[(size_t)r * HH + j];
        s += v; q += v * v;
    }
    g_psum[b * HH + j] = s;
    g_psq[b * HH + j]  = q;
}

__global__ void bn_final() {       // 1 block of 128
    int j = threadIdx.x;
    float s = 0.0f, q = 0.0f;
    for (int b = 0; b < 160; b++) { s += g_psum[b * HH + j]; q += g_psq[b * HH + j]; }
    float m = s / (float)TT;
    float var = q / (float)TT - m * m;
    g_mean[j] = m;
    g_rstd[j] = rsqrtf(var + 1e-5f);
}

__global__ void final_kernel(const float* __restrict__ Wout,
                             const float* __restrict__ bout,
                             const float* __restrict__ gamma,
                             const float* __restrict__ beta,
                             float* __restrict__ out) {
    int warp = (blockIdx.x * blockDim.x + threadIdx.x) >> 5;
    int lane = threadIdx.x & 31;
    if (warp >= TT) return;
    const float* h1 = g_h + (size_t)(LL - 1) * TT * HH + (size_t)warp * HH;
    float a0 = 0.f, a1 = 0.f, a2 = 0.f, a3 = 0.f;
    for (int k = lane; k < HH; k += 32) {
        float v = (h1[k] - g_mean[k]) * g_rstd[k] * gamma[k] + beta[k];
        v = fmaxf(v, 0.0f);
        a0 = fmaf(v, Wout[k * 4 + 0], a0);
        a1 = fmaf(v, Wout[k * 4 + 1], a1);
        a2 = fmaf(v, Wout[k * 4 + 2], a2);
        a3 = fmaf(v, Wout[k * 4 + 3], a3);
    }
#pragma unroll
    for (int o = 16; o; o >>= 1) {
        a0 += __shfl_xor_sync(0xFFFFFFFFu, a0, o);
        a1 += __shfl_xor_sync(0xFFFFFFFFu, a1, o);
        a2 += __shfl_xor_sync(0xFFFFFFFFu, a2, o);
        a3 += __shfl_xor_sync(0xFFFFFFFFu, a3, o);
    }
    if (lane == 0) {
        a0 += bout[0]; a1 += bout[1]; a2 += bout[2]; a3 += bout[3];
        float mx = fmaxf(fmaxf(a0, a1), fmaxf(a2, a3));
        float se = expf(a0 - mx) + expf(a1 - mx) + expf(a2 - mx) + expf(a3 - mx);
        float lse = mx + logf(se);
        out[(size_t)warp * 4 + 0] = a0 - lse;
        out[(size_t)warp * 4 + 1] = a1 - lse;
        out[(size_t)warp * 4 + 2] = a2 - lse;
        out[(size_t)warp * 4 + 3] = a3 - lse;
    }
}

// ---------------- host orchestration -----------------------------------------
extern "C" void kernel_launch(void* const* d_in, const int* in_sizes, int n_in,
                              void* d_out, int out_size) {
    const float* x_seq      = (const float*)d_in[0];
    const int*   edge_index = (const int*)  d_in[1];
    const float* edge_weight= (const float*)d_in[2];
    const float* lin_in_W   = (const float*)d_in[3];
    const float* lin_in_b   = (const float*)d_in[4];
    const float* convW      = (const float*)d_in[5];
    const float* convB      = (const float*)d_in[6];
    const float* bn_gamma   = (const float*)d_in[7];
    const float* bn_beta    = (const float*)d_in[8];
    const float* lin_out_W  = (const float*)d_in[9];
    const float* lin_out_b  = (const float*)d_in[10];
    float* out = (float*)d_out;
    (void)in_sizes; (void)n_in; (void)out_size;

    // graph preprocessing (deterministic CSR, rebuilt every call)
    k_prep_init <<<(NN + 255) / 256, 256>>>();
    k_prep_deg  <<<(EE + 255) / 256, 256>>>(edge_index, edge_weight);
    k_prep_dis  <<<(NN + 255) / 256, 256>>>();
    k_scan      <<<1, 1024>>>();
    k_fill_self <<<(NN + 255) / 256, 256>>>();
    k_fill_edges<<<(EE + 255) / 256, 256>>>(edge_index, edge_weight);
    k_sort      <<<(NN + 255) / 256, 256>>>();
    pack_wru    <<<(LL * 256 * 256 + 255) / 256, 256>>>(convW);
    zero_h      <<<((LL * TT * HH) + 255) / 256, 256>>>();

    dim3 gridRU((TT + BM - 1) / BM, 2);
    dim3 gridC ((TT + BM - 1) / BM, 1);

    for (int s = 0; s < SS; s++) {
        lin_in_kernel<<<TT, 128>>>(x_seq, lin_in_W, lin_in_b, s);
        for (int l = 0; l < LL; l++) {
            spmm_xh<<<TT, 256>>>(l);
            gemm_kernel<<<gridRU, 256>>>(0, l, convW, convB);
            spmm_rh<<<TT, 128>>>();
            gemm_kernel<<<gridC, 256>>>(1, l, convW, convB);
        }
    }

    bn_partial<<<160, 128>>>();
    bn_final<<<1, 128>>>();
    final_kernel<<<(TT * 32 + 255) / 256, 256>>>(lin_out_W, lin_out_b,
                                                 bn_gamma, bn_beta, out);
}

// round 3
// speedup vs baseline: 1.9731x; 1.9731x over previous
#include <cuda_runtime.h>
#include <math.h>
#include <cstdint>

#define NN 5000
#define BB 8
#define TT 40000      // BB*NN
#define EE 40000
#define SS 12
#define FF 16
#define HH 128
#define LL 2
#define NE (EE + NN)  // CSR entries (edges + self loops)

// ---------------- device scratch (static: no allocation allowed) ------------
__device__ float g_deg[NN];
__device__ float g_dis[NN];
__device__ int   g_cnt[NN];
__device__ int   g_ptr[NN + 1];
__device__ int   g_wpos[NN];
__device__ int   g_src[NE];
__device__ float g_wv[NE];
__device__ int   g_key[NE];

__device__ float g_Xt[(size_t)TT * HH];          // relu(lin_in) per step
__device__ float g_h[(size_t)LL * TT * HH];      // hidden states
__device__ float g_AXH[(size_t)TT * 2 * HH];     // [Ax | Ah] / [Ax | Arh]
__device__ float g_RH[(size_t)TT * HH];          // r * h
__device__ float g_U[(size_t)TT * HH];           // u gate
__device__ float g_WruT[(size_t)LL * 256 * 256]; // [n][k]: n<128 -> W_r, n>=128 -> W_u
__device__ float g_WcT[(size_t)LL * 128 * 256];  // [n][k] = W_c[k][n]
__device__ float g_psum[160 * HH];
__device__ float g_psq[160 * HH];
__device__ float g_mean[HH];
__device__ float g_rstd[HH];

__device__ __forceinline__ uint32_t f2tf32(float f) {
    uint32_t r;
    asm("cvt.rna.tf32.f32 %0, %1;" : "=r"(r) : "f"(f));
    return r;
}

// ---------------- graph preprocessing ---------------------------------------
__global__ void k_prep_init() {
    int i = blockIdx.x * blockDim.x + threadIdx.x;
    if (i < NN) { g_deg[i] = 1.0f; g_cnt[i] = 1; }
}

__global__ void k_prep_deg(const int* __restrict__ ei, const float* __restrict__ ew) {
    int e = blockIdx.x * blockDim.x + threadIdx.x;
    if (e < EE) {
        int c = ei[EE + e];
        atomicAdd(&g_deg[c], ew[e]);
        atomicAdd(&g_cnt[c], 1);
    }
}

__global__ void k_prep_dis() {
    int i = blockIdx.x * blockDim.x + threadIdx.x;
    if (i < NN) g_dis[i] = rsqrtf(g_deg[i]);
}

__global__ void k_scan() {
    __shared__ int sh[1024];
    __shared__ int carry;
    if (threadIdx.x == 0) carry = 0;
    __syncthreads();
    for (int base = 0; base < NN; base += 1024) {
        int i = base + threadIdx.x;
        int v = (i < NN) ? g_cnt[i] : 0;
        sh[threadIdx.x] = v;
        __syncthreads();
        for (int off = 1; off < 1024; off <<= 1) {
            int t = (threadIdx.x >= off) ? sh[threadIdx.x - off] : 0;
            __syncthreads();
            sh[threadIdx.x] += t;
            __syncthreads();
        }
        int excl = sh[threadIdx.x] - v + carry;
        if (i < NN) { g_ptr[i] = excl; }
        __syncthreads();
        if (threadIdx.x == 1023) carry += sh[1023];
        __syncthreads();
    }
    if (threadIdx.x == 0) g_ptr[NN] = carry;
}

__global__ void k_fill_self() {
    int i = blockIdx.x * blockDim.x + threadIdx.x;
    if (i < NN) {
        int p = g_ptr[i];
        g_src[p] = i;
        g_wv[p]  = g_dis[i] * g_dis[i];
        g_key[p] = -1;
        g_wpos[i] = p + 1;
    }
}

__global__ void k_fill_edges(const int* __restrict__ ei, const float* __restrict__ ew) {
    int e = blockIdx.x * blockDim.x + threadIdx.x;
    if (e < EE) {
        int r = ei[e];
        int c = ei[EE + e];
        int p = atomicAdd(&g_wpos[c], 1);
        g_src[p] = r;
        g_wv[p]  = g_dis[r] * ew[e] * g_dis[c];
        g_key[p] = e;
    }
}

__global__ void k_sort() {   // deterministic: self loop first, edges by id
    int c = blockIdx.x * blockDim.x + threadIdx.x;
    if (c >= NN) return;
    int s0 = g_ptr[c] + 1, s1 = g_ptr[c + 1];
    for (int i = s0 + 1; i < s1; i++) {
        int k = g_key[i]; int sr = g_src[i]; float w = g_wv[i];
        int j = i - 1;
        while (j >= s0 && g_key[j] > k) {
            g_key[j + 1] = g_key[j]; g_src[j + 1] = g_src[j]; g_wv[j + 1] = g_wv[j];
            j--;
        }
        g_key[j + 1] = k; g_src[j + 1] = sr; g_wv[j + 1] = w;
    }
}

__global__ void pack_wruT(const float* __restrict__ convW) {
    int i = blockIdx.x * blockDim.x + threadIdx.x;
    if (i < LL * 256 * 256) {
        int l = i >> 16, rem = i & 65535;
        int n = rem >> 8, k = rem & 255;
        int g = n >> 7, j = n & 127;
        g_WruT[i] = convW[((size_t)(l * 3 + g) * 256 + k) * 128 + j];
    }
}

__global__ void pack_wcT(const float* __restrict__ convW) {
    int i = blockIdx.x * blockDim.x + threadIdx.x;
    if (i < LL * 128 * 256) {
        int l = i >> 15, rem = i & 32767;
        int n = rem >> 8, k = rem & 255;
        g_WcT[i] = convW[((size_t)(l * 3 + 2) * 256 + k) * 128 + n];
    }
}

__global__ void zero_h() {
    size_t i = (size_t)blockIdx.x * blockDim.x + threadIdx.x;
    if (i < (size_t)LL * TT * HH) g_h[i] = 0.0f;
}

// ---------------- per-step kernels ------------------------------------------
__global__ void lin_in_kernel(const float* __restrict__ x_seq,
                              const float* __restrict__ W,
                              const float* __restrict__ bias, int s) {
    int t = blockIdx.x;
    int b = t / NN, n = t - b * NN;
    int j = threadIdx.x;
    __shared__ float xs[FF];
    if (j < FF) xs[j] = x_seq[(((size_t)b * SS + s) * NN + n) * FF + j];
    __syncthreads();
    float acc = bias[j];
#pragma unroll
    for (int k = 0; k < FF; k++) acc = fmaf(xs[k], W[k * HH + j], acc);
    g_Xt[(size_t)t * HH + j] = fmaxf(acc, 0.0f);
}

// AXH[:, 0:128] = Ahat @ x_in ; AXH[:, 128:256] = Ahat @ h_l
__global__ void spmm_xh(int l) {
    int t = blockIdx.x;
    int c = t % NN;
    int base = t - c;
    int j = threadIdx.x;               // 0..255
    const float* X = (l == 0) ? g_Xt : g_h;
    const float* src = (j < HH) ? X : (g_h + (size_t)l * TT * HH);
    int col = j & (HH - 1);
    int s0 = g_ptr[c], s1 = g_ptr[c + 1];
    float acc = 0.0f;
    for (int e = s0; e < s1; e++) {
        acc += g_wv[e] * src[(size_t)(base + g_src[e]) * HH + col];
    }
    g_AXH[(size_t)t * 256 + j] = acc;
}

// AXH[:, 128:256] = Ahat @ (r*h)
__global__ void spmm_rh() {
    int t = blockIdx.x;
    int c = t % NN;
    int base = t - c;
    int j = threadIdx.x;
    int s0 = g_ptr[c], s1 = g_ptr[c + 1];
    float acc = 0.0f;
    for (int e = s0; e < s1; e++) {
        acc += g_wv[e] * g_RH[(size_t)(base + g_src[e]) * HH + j];
    }
    g_AXH[(size_t)t * 256 + HH + j] = acc;
}

// ---------------- tf32 mma.sync GEMM with fused GRU epilogues -----------------
// C[40000 x 128] = AXH[40000 x 256] @ W-half, K in 8 chunks of 32.
// MODE 0: blockIdx.y selects gate half of WruT. y=0: RH = sigmoid(C+b_r)*h
//                                               y=1: U  = sigmoid(C+b_u)
// MODE 1: candidate. h = U*h + (1-U)*tanh(C+b_c)
#define LDM 36

__device__ __forceinline__ void mma_tf32_16n8k8(float* c, const uint32_t* a,
                                                const uint32_t* b) {
    asm volatile(
        "mma.sync.aligned.m16n8k8.row.col.f32.tf32.tf32.f32 "
        "{%0,%1,%2,%3}, {%4,%5,%6,%7}, {%8,%9}, {%0,%1,%2,%3};"
        : "+f"(c[0]), "+f"(c[1]), "+f"(c[2]), "+f"(c[3])
        : "r"(a[0]), "r"(a[1]), "r"(a[2]), "r"(a[3]), "r"(b[0]), "r"(b[1]));
}

template <int MODE>
__global__ void __launch_bounds__(256, 2) gemm_mma(int l, const float* __restrict__ convB) {
    __shared__ uint32_t As[128 * LDM];
    __shared__ uint32_t Bs[128 * LDM];

    int tid = threadIdx.x;
    int wid = tid >> 5, lane = tid & 31;
    int row_in = lane >> 2, kq = lane & 3;
    int wm = wid & 3, wn = wid >> 2;         // 4x2 warp grid
    int m0 = blockIdx.x * 128;
    int y  = blockIdx.y;                      // MODE0: gate (0=r, 1=u)

    const float* WT   = (MODE == 0) ? (g_WruT + (size_t)l * 256 * 256 + (size_t)y * 128 * 256)
                                    : (g_WcT  + (size_t)l * 128 * 256);
    const float* bias = (MODE == 0) ? (convB + (size_t)l * 3 * HH + (size_t)y * HH)
                                    : (convB + (size_t)(l * 3 + 2) * HH);

    float acc[2][8][4];
#pragma unroll
    for (int i = 0; i < 2; i++)
#pragma unroll
        for (int j = 0; j < 8; j++)
#pragma unroll
            for (int q = 0; q < 4; q++) acc[i][j][q] = 0.0f;

    for (int kc = 0; kc < 8; kc++) {
        int k0 = kc * 32;
        // A tile: 128 rows x 32 k (float4 loads, tf32 convert, stride-36 smem)
#pragma unroll
        for (int it = 0; it < 4; it++) {
            int idx = tid + it * 256;          // 0..1023
            int row = idx >> 3, q = idx & 7;
            int gm = m0 + row;
            float4 v = (gm < TT)
                ? *reinterpret_cast<const float4*>(&g_AXH[(size_t)gm * 256 + k0 + q * 4])
                : make_float4(0.f, 0.f, 0.f, 0.f);
            uint4 t;
            t.x = f2tf32(v.x); t.y = f2tf32(v.y); t.z = f2tf32(v.z); t.w = f2tf32(v.w);
            *reinterpret_cast<uint4*>(&As[row * LDM + q * 4]) = t;
        }
        // B tile: 128 n-rows x 32 k from WT[n][k]
#pragma unroll
        for (int it = 0; it < 4; it++) {
            int idx = tid + it * 256;
            int row = idx >> 3, q = idx & 7;
            float4 v = *reinterpret_cast<const float4*>(&WT[(size_t)row * 256 + k0 + q * 4]);
            uint4 t;
            t.x = f2tf32(v.x); t.y = f2tf32(v.y); t.z = f2tf32(v.z); t.w = f2tf32(v.w);
            *reinterpret_cast<uint4*>(&Bs[row * LDM + q * 4]) = t;
        }
        __syncthreads();
#pragma unroll
        for (int ks = 0; ks < 4; ks++) {
            int k8 = ks * 8;
            uint32_t a[2][4], b[8][2];
#pragma unroll
            for (int i = 0; i < 2; i++) {
                int m = wm * 32 + i * 16 + row_in;
                a[i][0] = As[m * LDM + k8 + kq];
                a[i][1] = As[(m + 8) * LDM + k8 + kq];
                a[i][2] = As[m * LDM + k8 + kq + 4];
                a[i][3] = As[(m + 8) * LDM + k8 + kq + 4];
            }
#pragma unroll
            for (int j = 0; j < 8; j++) {
                int n = wn * 64 + j * 8 + row_in;
                b[j][0] = Bs[n * LDM + k8 + kq];
                b[j][1] = Bs[n * LDM + k8 + kq + 4];
            }
#pragma unroll
            for (int i = 0; i < 2; i++)
#pragma unroll
                for (int j = 0; j < 8; j++)
                    mma_tf32_16n8k8(acc[i][j], a[i], b[j]);
        }
        __syncthreads();
    }

    // epilogue: c0,c1 -> (r0, n), (r0, n+1); c2,c3 -> (r0+8, ...)
    float* Hst = g_h + (size_t)l * TT * HH;
#pragma unroll
    for (int i = 0; i < 2; i++) {
        int r0 = m0 + wm * 32 + i * 16 + row_in;
#pragma unroll
        for (int half = 0; half < 2; half++) {
            int m = r0 + half * 8;
            if (m >= TT) continue;
#pragma unroll
            for (int j = 0; j < 8; j++) {
                int n = wn * 64 + j * 8 + 2 * kq;
                float v0 = acc[i][j][half * 2 + 0] + bias[n];
                float v1 = acc[i][j][half * 2 + 1] + bias[n + 1];
                size_t o = (size_t)m * HH + n;
                if (MODE == 0) {
                    float s0 = 1.0f / (1.0f + expf(-v0));
                    float s1 = 1.0f / (1.0f + expf(-v1));
                    if (y == 0) {
                        float2 hv = *reinterpret_cast<const float2*>(&Hst[o]);
                        float2 rv; rv.x = s0 * hv.x; rv.y = s1 * hv.y;
                        *reinterpret_cast<float2*>(&g_RH[o]) = rv;
                    } else {
                        float2 uv; uv.x = s0; uv.y = s1;
                        *reinterpret_cast<float2*>(&g_U[o]) = uv;
                    }
                } else {
                    float c0 = tanhf(v0), c1 = tanhf(v1);
                    float2 uv = *reinterpret_cast<const float2*>(&g_U[o]);
                    float2 hv = *reinterpret_cast<const float2*>(&Hst[o]);
                    hv.x = uv.x * hv.x + (1.0f - uv.x) * c0;
                    hv.y = uv.y * hv.y + (1.0f - uv.y) * c1;
                    *reinterpret_cast<float2*>(&Hst[o]) = hv;
                }
            }
        }
    }
}

// ---------------- batchnorm + output -----------------------------------------
__global__ void bn_partial() {
    int j = threadIdx.x;
    int b = blockIdx.x;
    const float* h1 = g_h + (size_t)(LL - 1) * TT * HH;
    float s = 0.0f, q = 0.0f;
    int r0 = b * (TT / 160), r1 = r0 + (TT / 160);
    for (int r = r0; r < r1; r++) {
        float v = h1[(size_t)r * HH + j];
        s += v; q += v * v;
    }
    g_psum[b * HH + j] = s;
    g_psq[b * HH + j]  = q;
}

__global__ void bn_final() {
    int j = threadIdx.x;
    float s = 0.0f, q = 0.0f;
    for (int b = 0; b < 160; b++) { s += g_psum[b * HH + j]; q += g_psq[b * HH + j]; }
    float m = s / (float)TT;
    float var = q / (float)TT - m * m;
    g_mean[j] = m;
    g_rstd[j] = rsqrtf(var + 1e-5f);
}

__global__ void final_kernel(const float* __restrict__ Wout,
                             const float* __restrict__ bout,
                             const float* __restrict__ gamma,
                             const float* __restrict__ beta,
                             float* __restrict__ out) {
    int warp = (blockIdx.x * blockDim.x + threadIdx.x) >> 5;
    int lane = threadIdx.x & 31;
    if (warp >= TT) return;
    const float* h1 = g_h + (size_t)(LL - 1) * TT * HH + (size_t)warp * HH;
    float a0 = 0.f, a1 = 0.f, a2 = 0.f, a3 = 0.f;
    for (int k = lane; k < HH; k += 32) {
        float v = (h1[k] - g_mean[k]) * g_rstd[k] * gamma[k] + beta[k];
        v = fmaxf(v, 0.0f);
        a0 = fmaf(v, Wout[k * 4 + 0], a0);
        a1 = fmaf(v, Wout[k * 4 + 1], a1);
        a2 = fmaf(v, Wout[k * 4 + 2], a2);
        a3 = fmaf(v, Wout[k * 4 + 3], a3);
    }
#pragma unroll
    for (int o = 16; o; o >>= 1) {
        a0 += __shfl_xor_sync(0xFFFFFFFFu, a0, o);
        a1 += __shfl_xor_sync(0xFFFFFFFFu, a1, o);
        a2 += __shfl_xor_sync(0xFFFFFFFFu, a2, o);
        a3 += __shfl_xor_sync(0xFFFFFFFFu, a3, o);
    }
    if (lane == 0) {
        a0 += bout[0]; a1 += bout[1]; a2 += bout[2]; a3 += bout[3];
        float mx = fmaxf(fmaxf(a0, a1), fmaxf(a2, a3));
        float se = expf(a0 - mx) + expf(a1 - mx) + expf(a2 - mx) + expf(a3 - mx);
        float lse = mx + logf(se);
        out[(size_t)warp * 4 + 0] = a0 - lse;
        out[(size_t)warp * 4 + 1] = a1 - lse;
        out[(size_t)warp * 4 + 2] = a2 - lse;
        out[(size_t)warp * 4 + 3] = a3 - lse;
    }
}

// ---------------- host orchestration -----------------------------------------
extern "C" void kernel_launch(void* const* d_in, const int* in_sizes, int n_in,
                              void* d_out, int out_size) {
    const float* x_seq      = (const float*)d_in[0];
    const int*   edge_index = (const int*)  d_in[1];
    const float* edge_weight= (const float*)d_in[2];
    const float* lin_in_W   = (const float*)d_in[3];
    const float* lin_in_b   = (const float*)d_in[4];
    const float* convW      = (const float*)d_in[5];
    const float* convB      = (const float*)d_in[6];
    const float* bn_gamma   = (const float*)d_in[7];
    const float* bn_beta    = (const float*)d_in[8];
    const float* lin_out_W  = (const float*)d_in[9];
    const float* lin_out_b  = (const float*)d_in[10];
    float* out = (float*)d_out;
    (void)in_sizes; (void)n_in; (void)out_size;

    // graph preprocessing (deterministic CSR, rebuilt every call)
    k_prep_init <<<(NN + 255) / 256, 256>>>();
    k_prep_deg  <<<(EE + 255) / 256, 256>>>(edge_index, edge_weight);
    k_prep_dis  <<<(NN + 255) / 256, 256>>>();
    k_scan      <<<1, 1024>>>();
    k_fill_self <<<(NN + 255) / 256, 256>>>();
    k_fill_edges<<<(EE + 255) / 256, 256>>>(edge_index, edge_weight);
    k_sort      <<<(NN + 255) / 256, 256>>>();
    pack_wruT   <<<(LL * 256 * 256 + 255) / 256, 256>>>(convW);
    pack_wcT    <<<(LL * 128 * 256 + 255) / 256, 256>>>(convW);
    zero_h      <<<((LL * TT * HH) + 255) / 256, 256>>>();

    dim3 gridRU((TT + 127) / 128, 2);
    dim3 gridC ((TT + 127) / 128, 1);

    for (int s = 0; s < SS; s++) {
        lin_in_kernel<<<TT, 128>>>(x_seq, lin_in_W, lin_in_b, s);
        for (int l = 0; l < LL; l++) {
            spmm_xh<<<TT, 256>>>(l);
            gemm_mma<0><<<gridRU, 256>>>(l, convB);
            spmm_rh<<<TT, 128>>>();
            gemm_mma<1><<<gridC, 256>>>(l, convB);
        }
    }

    bn_partial<<<160, 128>>>();
    bn_final<<<1, 128>>>();
    final_kernel<<<(TT * 32 + 255) / 256, 256>>>(lin_out_W, lin_out_b,
                                                 bn_gamma, bn_beta, out);
}

// round 4
// speedup vs baseline: 3.0385x; 1.5400x over previous
#include <cuda_runtime.h>
#include <cuda_fp16.h>
#include <math.h>
#include <cstdint>

#define NN 5000
#define BB 8
#define TT 40000      // BB*NN
#define EE 40000
#define SS 12
#define FF 16
#define HH 128
#define LL 2
#define NE (EE + NN)  // CSR entries (edges + self loops)

// ---------------- device scratch (static: no allocation allowed) ------------
__device__ float g_deg[NN];
__device__ float g_dis[NN];
__device__ int   g_cnt[NN];
__device__ int   g_ptr[NN + 1];
__device__ int   g_wpos[NN];
__device__ int   g_src[NE];
__device__ float g_wv[NE];
__device__ int   g_key[NE];

__device__ float  g_Xt[(size_t)SS * TT * HH];     // relu(lin_in), all steps, fp32
__device__ float  g_h[(size_t)LL * TT * HH];      // hidden states fp32
__device__ __half g_AXH[(size_t)TT * 2 * HH];     // [Ax | Ah] / [Ax | Arh] fp16
__device__ float  g_RH[(size_t)TT * HH];          // r * h fp32
__device__ float  g_U[(size_t)TT * HH];           // u gate fp32
__device__ __half g_WruT[(size_t)LL * 256 * 256]; // [n][k] fp16: n<128 W_r, n>=128 W_u
__device__ __half g_WcT[(size_t)LL * 128 * 256];  // [n][k] fp16
__device__ float  g_psum[160 * HH];
__device__ float  g_psq[160 * HH];
__device__ float  g_mean[HH];
__device__ float  g_rstd[HH];

// ---------------- single-block cooperative graph prep -----------------------
__global__ void prep_all(const int* __restrict__ ei, const float* __restrict__ ew) {
    int tid = threadIdx.x;                       // 1024 threads, 1 block
    // 1: init
    for (int i = tid; i < NN; i += 1024) { g_deg[i] = 1.0f; g_cnt[i] = 1; }
    __syncthreads();
    // 2: degree accumulation
    for (int e = tid; e < EE; e += 1024) {
        int c = ei[EE + e];
        atomicAdd(&g_deg[c], ew[e]);
        atomicAdd(&g_cnt[c], 1);
    }
    __syncthreads();
    // 3: dis
    for (int i = tid; i < NN; i += 1024) g_dis[i] = rsqrtf(g_deg[i]);
    __syncthreads();
    // 4: exclusive scan of cnt -> ptr
    __shared__ int sh[1024];
    __shared__ int carry;
    if (tid == 0) carry = 0;
    __syncthreads();
    for (int base = 0; base < NN; base += 1024) {
        int i = base + tid;
        int v = (i < NN) ? g_cnt[i] : 0;
        sh[tid] = v;
        __syncthreads();
        for (int off = 1; off < 1024; off <<= 1) {
            int t = (tid >= off) ? sh[tid - off] : 0;
            __syncthreads();
            sh[tid] += t;
            __syncthreads();
        }
        int excl = sh[tid] - v + carry;
        if (i < NN) g_ptr[i] = excl;
        __syncthreads();
        if (tid == 1023) carry += sh[1023];
        __syncthreads();
    }
    if (tid == 0) g_ptr[NN] = carry;
    __syncthreads();
    // 5: self loops
    for (int i = tid; i < NN; i += 1024) {
        int p = g_ptr[i];
        g_src[p] = i;
        g_wv[p]  = g_dis[i] * g_dis[i];
        g_key[p] = -1;
        g_wpos[i] = p + 1;
    }
    __syncthreads();
    // 6: edges
    for (int e = tid; e < EE; e += 1024) {
        int r = ei[e];
        int c = ei[EE + e];
        int p = atomicAdd(&g_wpos[c], 1);
        g_src[p] = r;
        g_wv[p]  = g_dis[r] * ew[e] * g_dis[c];
        g_key[p] = e;
    }
    __syncthreads();
    // 7: deterministic per-column sort (self loop first, edges by id)
    for (int c = tid; c < NN; c += 1024) {
        int s0 = g_ptr[c] + 1, s1 = g_ptr[c + 1];
        for (int i = s0 + 1; i < s1; i++) {
            int k = g_key[i]; int sr = g_src[i]; float w = g_wv[i];
            int j = i - 1;
            while (j >= s0 && g_key[j] > k) {
                g_key[j + 1] = g_key[j]; g_src[j + 1] = g_src[j]; g_wv[j + 1] = g_wv[j];
                j--;
            }
            g_key[j + 1] = k; g_src[j + 1] = sr; g_wv[j + 1] = w;
        }
    }
}

// ---------------- weight packing (fp16) + zero h, fused ----------------------
#define W1 (LL * 256 * 256)
#define W2 (LL * 128 * 256)
#define W3 ((size_t)LL * TT * HH)
__global__ void init_misc(const float* __restrict__ convW) {
    size_t i = (size_t)blockIdx.x * blockDim.x + threadIdx.x;
    if (i < W1) {
        int l = (int)(i >> 16), rem = (int)(i & 65535);
        int n = rem >> 8, k = rem & 255;
        int g = n >> 7, j = n & 127;
        g_WruT[i] = __float2half(convW[((size_t)(l * 3 + g) * 256 + k) * 128 + j]);
    } else if (i < W1 + W2) {
        size_t q = i - W1;
        int l = (int)(q >> 15), rem = (int)(q & 32767);
        int n = rem >> 8, k = rem & 255;
        g_WcT[q] = __float2half(convW[((size_t)(l * 3 + 2) * 256 + k) * 128 + n]);
    } else if (i < W1 + W2 + W3) {
        g_h[i - W1 - W2] = 0.0f;
    }
}

// ---------------- lin_in for all 12 steps ------------------------------------
__global__ void lin_in_all(const float* __restrict__ x_seq,
                           const float* __restrict__ W,
                           const float* __restrict__ bias) {
    int t2 = blockIdx.x;                 // 0 .. SS*TT-1
    int s = t2 / TT, t = t2 - s * TT;
    int b = t / NN, n = t - b * NN;
    int j = threadIdx.x;                 // 0..127
    __shared__ float xs[FF];
    if (j < FF) xs[j] = x_seq[(((size_t)b * SS + s) * NN + n) * FF + j];
    __syncthreads();
    float acc = bias[j];
#pragma unroll
    for (int k = 0; k < FF; k++) acc = fmaf(xs[k], W[k * HH + j], acc);
    g_Xt[(size_t)s * TT * HH + (size_t)t * HH + j] = fmaxf(acc, 0.0f);
}

// ---------------- SpMM gathers (fp32 in, fp16 out) ---------------------------
// AXH[:, 0:128] = Ahat @ x_in ; AXH[:, 128:256] = Ahat @ h_l
__global__ void spmm_xh(int l, int s) {
    int t = blockIdx.x;
    int c = t % NN;
    int base = t - c;
    int j = threadIdx.x;               // 0..255
    const float* X = (l == 0) ? (g_Xt + (size_t)s * TT * HH) : g_h;
    const float* src = (j < HH) ? X : (g_h + (size_t)l * TT * HH);
    int col = j & (HH - 1);
    int s0 = g_ptr[c], s1 = g_ptr[c + 1];
    float acc = 0.0f;
    int e = s0;
    for (; e + 4 <= s1; e += 4) {
        int i0 = g_src[e], i1 = g_src[e + 1], i2 = g_src[e + 2], i3 = g_src[e + 3];
        float w0 = g_wv[e], w1 = g_wv[e + 1], w2 = g_wv[e + 2], w3 = g_wv[e + 3];
        float v0 = src[(size_t)(base + i0) * HH + col];
        float v1 = src[(size_t)(base + i1) * HH + col];
        float v2 = src[(size_t)(base + i2) * HH + col];
        float v3 = src[(size_t)(base + i3) * HH + col];
        acc = fmaf(w0, v0, acc); acc = fmaf(w1, v1, acc);
        acc = fmaf(w2, v2, acc); acc = fmaf(w3, v3, acc);
    }
    for (; e < s1; e++)
        acc = fmaf(g_wv[e], src[(size_t)(base + g_src[e]) * HH + col], acc);
    g_AXH[(size_t)t * 256 + j] = __float2half(acc);
}

// AXH[:, 128:256] = Ahat @ (r*h)
__global__ void spmm_rh() {
    int t = blockIdx.x;
    int c = t % NN;
    int base = t - c;
    int j = threadIdx.x;               // 0..127
    int s0 = g_ptr[c], s1 = g_ptr[c + 1];
    float acc = 0.0f;
    int e = s0;
    for (; e + 4 <= s1; e += 4) {
        int i0 = g_src[e], i1 = g_src[e + 1], i2 = g_src[e + 2], i3 = g_src[e + 3];
        float w0 = g_wv[e], w1 = g_wv[e + 1], w2 = g_wv[e + 2], w3 = g_wv[e + 3];
        float v0 = g_RH[(size_t)(base + i0) * HH + j];
        float v1 = g_RH[(size_t)(base + i1) * HH + j];
        float v2 = g_RH[(size_t)(base + i2) * HH + j];
        float v3 = g_RH[(size_t)(base + i3) * HH + j];
        acc = fmaf(w0, v0, acc); acc = fmaf(w1, v1, acc);
        acc = fmaf(w2, v2, acc); acc = fmaf(w3, v3, acc);
    }
    for (; e < s1; e++)
        acc = fmaf(g_wv[e], g_RH[(size_t)(base + g_src[e]) * HH + j], acc);
    g_AXH[(size_t)t * 256 + HH + j] = __float2half(acc);
}

// ---------------- fp16 mma.sync GEMM with fused GRU epilogues ----------------
// C[40000 x 128] = AXH[40000 x 256] @ W-half (fp16 operands, fp32 accumulate).
// K = 256 in 4 chunks of 64 halves.
// MODE 0: blockIdx.y gate. y=0: RH = sigmoid(C+b_r)*h ; y=1: U = sigmoid(C+b_u)
// MODE 1: candidate. h = U*h + (1-U)*tanh(C+b_c)
#define LDM 36

__device__ __forceinline__ void mma_f16(float* c, const uint32_t* a, const uint32_t* b) {
    asm volatile(
        "mma.sync.aligned.m16n8k16.row.col.f32.f16.f16.f32 "
        "{%0,%1,%2,%3}, {%4,%5,%6,%7}, {%8,%9}, {%0,%1,%2,%3};"
        : "+f"(c[0]), "+f"(c[1]), "+f"(c[2]), "+f"(c[3])
        : "r"(a[0]), "r"(a[1]), "r"(a[2]), "r"(a[3]), "r"(b[0]), "r"(b[1]));
}

template <int MODE>
__global__ void __launch_bounds__(256) gemm_mma(int l, const float* __restrict__ convB) {
    __shared__ uint32_t As[128 * LDM];   // 128 rows x 32 half2 (+pad)
    __shared__ uint32_t Bs[128 * LDM];

    int tid = threadIdx.x;
    int wid = tid >> 5, lane = tid & 31;
    int row_in = lane >> 2, kq = lane & 3;
    int wm = wid & 3, wn = wid >> 2;         // 4x2 warp grid, warp tile 32x64
    int m0 = blockIdx.x * 128;
    int y  = blockIdx.y;

    const __half* WT  = (MODE == 0) ? (g_WruT + (size_t)l * 256 * 256 + (size_t)y * 128 * 256)
                                    : (g_WcT  + (size_t)l * 128 * 256);
    const float* bias = (MODE == 0) ? (convB + (size_t)l * 3 * HH + (size_t)y * HH)
                                    : (convB + (size_t)(l * 3 + 2) * HH);

    float acc[2][8][4];
#pragma unroll
    for (int i = 0; i < 2; i++)
#pragma unroll
        for (int j = 0; j < 8; j++)
#pragma unroll
            for (int q = 0; q < 4; q++) acc[i][j][q] = 0.0f;

    uint4 pa[4];
    // prefetch A chunk 0
#pragma unroll
    for (int it = 0; it < 4; it++) {
        int idx = tid + it * 256;            // 0..1023: 128 rows x 8 slots of 16B
        int row = idx >> 3, q = idx & 7;
        int gm = m0 + row;
        pa[it] = (gm < TT)
            ? *reinterpret_cast<const uint4*>(g_AXH + (size_t)gm * 256 + q * 8)
            : make_uint4(0u, 0u, 0u, 0u);
    }

    for (int kc = 0; kc < 4; kc++) {
        // store A regs -> smem ; load B gmem -> smem
#pragma unroll
        for (int it = 0; it < 4; it++) {
            int idx = tid + it * 256;
            int row = idx >> 3, q = idx & 7;
            *reinterpret_cast<uint4*>(&As[row * LDM + q * 4]) = pa[it];
        }
#pragma unroll
        for (int it = 0; it < 4; it++) {
            int idx = tid + it * 256;
            int row = idx >> 3, q = idx & 7;
            uint4 v = *reinterpret_cast<const uint4*>(WT + (size_t)row * 256 + kc * 64 + q * 8);
            *reinterpret_cast<uint4*>(&Bs[row * LDM + q * 4]) = v;
        }
        __syncthreads();
        // prefetch next A chunk
        if (kc < 3) {
#pragma unroll
            for (int it = 0; it < 4; it++) {
                int idx = tid + it * 256;
                int row = idx >> 3, q = idx & 7;
                int gm = m0 + row;
                pa[it] = (gm < TT)
                    ? *reinterpret_cast<const uint4*>(g_AXH + (size_t)gm * 256 + (kc + 1) * 64 + q * 8)
                    : make_uint4(0u, 0u, 0u, 0u);
            }
        }
        // compute: 4 k16 steps
#pragma unroll
        for (int ks = 0; ks < 4; ks++) {
            int k8 = ks * 8;
            uint32_t a[2][4], b[8][2];
#pragma unroll
            for (int i = 0; i < 2; i++) {
                int m = wm * 32 + i * 16 + row_in;
                a[i][0] = As[m * LDM + k8 + kq];
                a[i][1] = As[(m + 8) * LDM + k8 + kq];
                a[i][2] = As[m * LDM + k8 + kq + 4];
                a[i][3] = As[(m + 8) * LDM + k8 + kq + 4];
            }
#pragma unroll
            for (int j = 0; j < 8; j++) {
                int n = wn * 64 + j * 8 + row_in;
                b[j][0] = Bs[n * LDM + k8 + kq];
                b[j][1] = Bs[n * LDM + k8 + kq + 4];
            }
#pragma unroll
            for (int i = 0; i < 2; i++)
#pragma unroll
                for (int j = 0; j < 8; j++)
                    mma_f16(acc[i][j], a[i], b[j]);
        }
        __syncthreads();
    }

    // epilogue: c0,c1 -> (r, n,n+1); c2,c3 -> (r+8, ...)
    float* Hst = g_h + (size_t)l * TT * HH;
#pragma unroll
    for (int i = 0; i < 2; i++) {
        int r0 = m0 + wm * 32 + i * 16 + row_in;
#pragma unroll
        for (int half = 0; half < 2; half++) {
            int m = r0 + half * 8;
            if (m >= TT) continue;
#pragma unroll
            for (int j = 0; j < 8; j++) {
                int n = wn * 64 + j * 8 + 2 * kq;
                float v0 = acc[i][j][half * 2 + 0] + bias[n];
                float v1 = acc[i][j][half * 2 + 1] + bias[n + 1];
                size_t o = (size_t)m * HH + n;
                if (MODE == 0) {
                    float s0 = 1.0f / (1.0f + expf(-v0));
                    float s1 = 1.0f / (1.0f + expf(-v1));
                    if (y == 0) {
                        float2 hv = *reinterpret_cast<const float2*>(&Hst[o]);
                        float2 rv; rv.x = s0 * hv.x; rv.y = s1 * hv.y;
                        *reinterpret_cast<float2*>(&g_RH[o]) = rv;
                    } else {
                        float2 uv; uv.x = s0; uv.y = s1;
                        *reinterpret_cast<float2*>(&g_U[o]) = uv;
                    }
                } else {
                    float c0 = tanhf(v0), c1 = tanhf(v1);
                    float2 uv = *reinterpret_cast<const float2*>(&g_U[o]);
                    float2 hv = *reinterpret_cast<const float2*>(&Hst[o]);
                    hv.x = uv.x * hv.x + (1.0f - uv.x) * c0;
                    hv.y = uv.y * hv.y + (1.0f - uv.y) * c1;
                    *reinterpret_cast<float2*>(&Hst[o]) = hv;
                }
            }
        }
    }
}

// ---------------- batchnorm + output -----------------------------------------
__global__ void bn_partial() {
    int j = threadIdx.x;
    int b = blockIdx.x;
    const float* h1 = g_h + (size_t)(LL - 1) * TT * HH;
    float s = 0.0f, q = 0.0f;
    int r0 = b * (TT / 160), r1 = r0 + (TT / 160);
    for (int r = r0; r < r1; r++) {
        float v = h1[(size_t)r * HH + j];
        s += v; q += v * v;
    }
    g_psum[b * HH + j] = s;
    g_psq[b * HH + j]  = q;
}

__global__ void bn_final() {
    int j = threadIdx.x;
    float s = 0.0f, q = 0.0f;
    for (int b = 0; b < 160; b++) { s += g_psum[b * HH + j]; q += g_psq[b * HH + j]; }
    float m = s / (float)TT;
    float var = q / (float)TT - m * m;
    g_mean[j] = m;
    g_rstd[j] = rsqrtf(var + 1e-5f);
}

__global__ void final_kernel(const float* __restrict__ Wout,
                             const float* __restrict__ bout,
                             const float* __restrict__ gamma,
                             const float* __restrict__ beta,
                             float* __restrict__ out) {
    int warp = (blockIdx.x * blockDim.x + threadIdx.x) >> 5;
    int lane = threadIdx.x & 31;
    if (warp >= TT) return;
    const float* h1 = g_h + (size_t)(LL - 1) * TT * HH + (size_t)warp * HH;
    float a0 = 0.f, a1 = 0.f, a2 = 0.f, a3 = 0.f;
    for (int k = lane; k < HH; k += 32) {
        float v = (h1[k] - g_mean[k]) * g_rstd[k] * gamma[k] + beta[k];
        v = fmaxf(v, 0.0f);
        a0 = fmaf(v, Wout[k * 4 + 0], a0);
        a1 = fmaf(v, Wout[k * 4 + 1], a1);
        a2 = fmaf(v, Wout[k * 4 + 2], a2);
        a3 = fmaf(v, Wout[k * 4 + 3], a3);
    }
#pragma unroll
    for (int o = 16; o; o >>= 1) {
        a0 += __shfl_xor_sync(0xFFFFFFFFu, a0, o);
        a1 += __shfl_xor_sync(0xFFFFFFFFu, a1, o);
        a2 += __shfl_xor_sync(0xFFFFFFFFu, a2, o);
        a3 += __shfl_xor_sync(0xFFFFFFFFu, a3, o);
    }
    if (lane == 0) {
        a0 += bout[0]; a1 += bout[1]; a2 += bout[2]; a3 += bout[3];
        float mx = fmaxf(fmaxf(a0, a1), fmaxf(a2, a3));
        float se = expf(a0 - mx) + expf(a1 - mx) + expf(a2 - mx) + expf(a3 - mx);
        float lse = mx + logf(se);
        out[(size_t)warp * 4 + 0] = a0 - lse;
        out[(size_t)warp * 4 + 1] = a1 - lse;
        out[(size_t)warp * 4 + 2] = a2 - lse;
        out[(size_t)warp * 4 + 3] = a3 - lse;
    }
}

// ---------------- host orchestration -----------------------------------------
extern "C" void kernel_launch(void* const* d_in, const int* in_sizes, int n_in,
                              void* d_out, int out_size) {
    const float* x_seq      = (const float*)d_in[0];
    const int*   edge_index = (const int*)  d_in[1];
    const float* edge_weight= (const float*)d_in[2];
    const float* lin_in_W   = (const float*)d_in[3];
    const float* lin_in_b   = (const float*)d_in[4];
    const float* convW      = (const float*)d_in[5];
    const float* convB      = (const float*)d_in[6];
    const float* bn_gamma   = (const float*)d_in[7];
    const float* bn_beta    = (const float*)d_in[8];
    const float* lin_out_W  = (const float*)d_in[9];
    const float* lin_out_b  = (const float*)d_in[10];
    float* out = (float*)d_out;
    (void)in_sizes; (void)n_in; (void)out_size;

    // launch #1..#3 (launch #4 = first spmm_xh -> lands in the ncu window)
    prep_all<<<1, 1024>>>(edge_index, edge_weight);
    size_t misc_items = (size_t)W1 + W2 + W3;
    init_misc<<<(unsigned)((misc_items + 255) / 256), 256>>>(convW);
    lin_in_all<<<SS * TT, 128>>>(x_seq, lin_in_W, lin_in_b);

    dim3 gridRU((TT + 127) / 128, 2);
    dim3 gridC ((TT + 127) / 128, 1);

    for (int s = 0; s < SS; s++) {
        for (int l = 0; l < LL; l++) {
            spmm_xh<<<TT, 256>>>(l, s);
            gemm_mma<0><<<gridRU, 256>>>(l, convB);
            spmm_rh<<<TT, 128>>>();
            gemm_mma<1><<<gridC, 256>>>(l, convB);
        }
    }

    bn_partial<<<160, 128>>>();
    bn_final<<<1, 128>>>();
    final_kernel<<<(TT * 32 + 255) / 256, 256>>>(lin_out_W, lin_out_b,
                                                 bn_gamma, bn_beta, out);
}

// round 5
// speedup vs baseline: 3.4256x; 1.1274x over previous
#include <cuda_runtime.h>
#include <cuda_fp16.h>
#include <math.h>
#include <cstdint>

#define NN 5000
#define BB 8
#define TT 40000      // BB*NN
#define EE 40000
#define SS 12
#define FF 16
#define HH 128
#define LL 2
#define NE (EE + NN)  // CSR entries (edges + self loops)

// ---------------- device scratch (static: no allocation allowed) ------------
__device__ float g_deg[NN];
__device__ float g_dis[NN];
__device__ int   g_cnt[NN];
__device__ int   g_ptr[NN + 1];
__device__ int   g_wpos[NN];
__device__ int   g_src[NE];
__device__ float g_wv[NE];
__device__ int   g_key[NE];

__device__ float  g_Xt[(size_t)SS * TT * HH];     // relu(lin_in), all steps, fp32
__device__ float  g_h[(size_t)LL * TT * HH];      // hidden states fp32
__device__ __half g_AXH[(size_t)TT * 2 * HH];     // [Ax | Ah] / [Ax | Arh] fp16
__device__ float  g_RH[(size_t)TT * HH];          // r * h fp32
__device__ float  g_U[(size_t)TT * HH];           // u gate fp32
__device__ __half g_WruT[(size_t)LL * 256 * 256]; // [n][k] fp16: n<128 W_r, n>=128 W_u
__device__ __half g_WcT[(size_t)LL * 128 * 256];  // [n][k] fp16
__device__ float  g_psum[160 * HH];
__device__ float  g_psq[160 * HH];
__device__ float  g_mean[HH];
__device__ float  g_rstd[HH];

// ---------------- single-block cooperative graph prep -----------------------
__global__ void prep_all(const int* __restrict__ ei, const float* __restrict__ ew) {
    int tid = threadIdx.x;                       // 1024 threads, 1 block
    for (int i = tid; i < NN; i += 1024) { g_deg[i] = 1.0f; g_cnt[i] = 1; }
    __syncthreads();
    for (int e = tid; e < EE; e += 1024) {
        int c = ei[EE + e];
        atomicAdd(&g_deg[c], ew[e]);
        atomicAdd(&g_cnt[c], 1);
    }
    __syncthreads();
    for (int i = tid; i < NN; i += 1024) g_dis[i] = rsqrtf(g_deg[i]);
    __syncthreads();
    __shared__ int sh[1024];
    __shared__ int carry;
    if (tid == 0) carry = 0;
    __syncthreads();
    for (int base = 0; base < NN; base += 1024) {
        int i = base + tid;
        int v = (i < NN) ? g_cnt[i] : 0;
        sh[tid] = v;
        __syncthreads();
        for (int off = 1; off < 1024; off <<= 1) {
            int t = (tid >= off) ? sh[tid - off] : 0;
            __syncthreads();
            sh[tid] += t;
            __syncthreads();
        }
        int excl = sh[tid] - v + carry;
        if (i < NN) g_ptr[i] = excl;
        __syncthreads();
        if (tid == 1023) carry += sh[1023];
        __syncthreads();
    }
    if (tid == 0) g_ptr[NN] = carry;
    __syncthreads();
    for (int i = tid; i < NN; i += 1024) {
        int p = g_ptr[i];
        g_src[p] = i;
        g_wv[p]  = g_dis[i] * g_dis[i];
        g_key[p] = -1;
        g_wpos[i] = p + 1;
    }
    __syncthreads();
    for (int e = tid; e < EE; e += 1024) {
        int r = ei[e];
        int c = ei[EE + e];
        int p = atomicAdd(&g_wpos[c], 1);
        g_src[p] = r;
        g_wv[p]  = g_dis[r] * ew[e] * g_dis[c];
        g_key[p] = e;
    }
    __syncthreads();
    for (int c = tid; c < NN; c += 1024) {
        int s0 = g_ptr[c] + 1, s1 = g_ptr[c + 1];
        for (int i = s0 + 1; i < s1; i++) {
            int k = g_key[i]; int sr = g_src[i]; float w = g_wv[i];
            int j = i - 1;
            while (j >= s0 && g_key[j] > k) {
                g_key[j + 1] = g_key[j]; g_src[j + 1] = g_src[j]; g_wv[j + 1] = g_wv[j];
                j--;
            }
            g_key[j + 1] = k; g_src[j + 1] = sr; g_wv[j + 1] = w;
        }
    }
}

// --------- fused: weight pack (fp16) + zero h + lin_in (all steps) -----------
#define W1 (LL * 256 * 256)
#define W2 (LL * 128 * 256)
#define W3 (LL * TT * HH)
#define MISC_BLOCKS ((W1 + W2 + W3 + 127) / 128)

__global__ void init_and_linin(const float* __restrict__ convW,
                               const float* __restrict__ x_seq,
                               const float* __restrict__ W,
                               const float* __restrict__ bias) {
    if (blockIdx.x < MISC_BLOCKS) {
        size_t i = (size_t)blockIdx.x * 128 + threadIdx.x;
        if (i < W1) {
            int l = (int)(i >> 16), rem = (int)(i & 65535);
            int n = rem >> 8, k = rem & 255;
            int g = n >> 7, j = n & 127;
            g_WruT[i] = __float2half(convW[((size_t)(l * 3 + g) * 256 + k) * 128 + j]);
        } else if (i < (size_t)W1 + W2) {
            size_t q = i - W1;
            int l = (int)(q >> 15), rem = (int)(q & 32767);
            int n = rem >> 8, k = rem & 255;
            g_WcT[q] = __float2half(convW[((size_t)(l * 3 + 2) * 256 + k) * 128 + n]);
        } else if (i < (size_t)W1 + W2 + W3) {
            g_h[i - W1 - W2] = 0.0f;
        }
    } else {
        int t2 = blockIdx.x - MISC_BLOCKS;   // 0 .. SS*TT-1
        int s = t2 / TT, t = t2 - s * TT;
        int b = t / NN, n = t - b * NN;
        int j = threadIdx.x;                 // 0..127
        __shared__ float xs[FF];
        if (j < FF) xs[j] = x_seq[(((size_t)b * SS + s) * NN + n) * FF + j];
        __syncthreads();
        float acc = bias[j];
#pragma unroll
        for (int k = 0; k < FF; k++) acc = fmaf(xs[k], W[k * HH + j], acc);
        g_Xt[(size_t)s * TT * HH + (size_t)t * HH + j] = fmaxf(acc, 0.0f);
    }
}

// ---------------- SpMM gathers (fp32 in, fp16 out), 32-bit addressing --------
// One block per node t (128 threads). Each thread computes BOTH halves, reusing
// the edge offset: AXH[t][j] = sum_e w_e * X[base+src_e][j]
//                  AXH[t][128+j] = sum_e w_e * H[base+src_e][j]
__global__ void __launch_bounds__(128) spmm_xh(int l, int s) {
    int t = blockIdx.x;
    int c = t % NN;
    int base = t - c;
    int j = threadIdx.x;               // 0..127
    const float* X = (l == 0) ? (g_Xt + (size_t)s * TT * HH) : g_h;
    const float* H = g_h + (size_t)l * TT * HH;
    const float* px = X + base * HH + j;
    const float* ph = H + base * HH + j;
    int s0 = g_ptr[c], s1 = g_ptr[c + 1];
    float ax = 0.0f, ah = 0.0f;
    int e = s0;
    for (; e + 4 <= s1; e += 4) {
        int o0 = g_src[e] * HH,     o1 = g_src[e + 1] * HH;
        int o2 = g_src[e + 2] * HH, o3 = g_src[e + 3] * HH;
        float w0 = g_wv[e],     w1 = g_wv[e + 1];
        float w2 = g_wv[e + 2], w3 = g_wv[e + 3];
        float x0 = __ldg(px + o0), x1 = __ldg(px + o1);
        float x2 = __ldg(px + o2), x3 = __ldg(px + o3);
        float h0 = __ldg(ph + o0), h1 = __ldg(ph + o1);
        float h2 = __ldg(ph + o2), h3 = __ldg(ph + o3);
        ax = fmaf(w0, x0, ax); ah = fmaf(w0, h0, ah);
        ax = fmaf(w1, x1, ax); ah = fmaf(w1, h1, ah);
        ax = fmaf(w2, x2, ax); ah = fmaf(w2, h2, ah);
        ax = fmaf(w3, x3, ax); ah = fmaf(w3, h3, ah);
    }
    for (; e < s1; e++) {
        int o = g_src[e] * HH;
        float w = g_wv[e];
        ax = fmaf(w, __ldg(px + o), ax);
        ah = fmaf(w, __ldg(ph + o), ah);
    }
    g_AXH[t * 256 + j] = __float2half(ax);
    g_AXH[t * 256 + 128 + j] = __float2half(ah);
}

// AXH[:, 128:256] = Ahat @ (r*h)
__global__ void __launch_bounds__(128) spmm_rh() {
    int t = blockIdx.x;
    int c = t % NN;
    int base = t - c;
    int j = threadIdx.x;               // 0..127
    const float* pr = g_RH + base * HH + j;
    int s0 = g_ptr[c], s1 = g_ptr[c + 1];
    float acc = 0.0f;
    int e = s0;
    for (; e + 4 <= s1; e += 4) {
        int o0 = g_src[e] * HH,     o1 = g_src[e + 1] * HH;
        int o2 = g_src[e + 2] * HH, o3 = g_src[e + 3] * HH;
        float w0 = g_wv[e],     w1 = g_wv[e + 1];
        float w2 = g_wv[e + 2], w3 = g_wv[e + 3];
        float v0 = __ldg(pr + o0), v1 = __ldg(pr + o1);
        float v2 = __ldg(pr + o2), v3 = __ldg(pr + o3);
        acc = fmaf(w0, v0, acc); acc = fmaf(w1, v1, acc);
        acc = fmaf(w2, v2, acc); acc = fmaf(w3, v3, acc);
    }
    for (; e < s1; e++)
        acc = fmaf(g_wv[e], __ldg(pr + g_src[e] * HH), acc);
    g_AXH[t * 256 + 128 + j] = __float2half(acc);
}

// ---------------- fp16 mma.sync GEMM with fused GRU epilogues ----------------
#define LDM 36

__device__ __forceinline__ void mma_f16(float* c, const uint32_t* a, const uint32_t* b) {
    asm volatile(
        "mma.sync.aligned.m16n8k16.row.col.f32.f16.f16.f32 "
        "{%0,%1,%2,%3}, {%4,%5,%6,%7}, {%8,%9}, {%0,%1,%2,%3};"
        : "+f"(c[0]), "+f"(c[1]), "+f"(c[2]), "+f"(c[3])
        : "r"(a[0]), "r"(a[1]), "r"(a[2]), "r"(a[3]), "r"(b[0]), "r"(b[1]));
}

template <int MODE>
__global__ void __launch_bounds__(256) gemm_mma(int l, const float* __restrict__ convB) {
    __shared__ uint32_t As[128 * LDM];
    __shared__ uint32_t Bs[128 * LDM];

    int tid = threadIdx.x;
    int wid = tid >> 5, lane = tid & 31;
    int row_in = lane >> 2, kq = lane & 3;
    int wm = wid & 3, wn = wid >> 2;
    int m0 = blockIdx.x * 128;
    int y  = blockIdx.y;

    const __half* WT  = (MODE == 0) ? (g_WruT + (size_t)l * 256 * 256 + (size_t)y * 128 * 256)
                                    : (g_WcT  + (size_t)l * 128 * 256);
    const float* bias = (MODE == 0) ? (convB + (size_t)l * 3 * HH + (size_t)y * HH)
                                    : (convB + (size_t)(l * 3 + 2) * HH);

    float acc[2][8][4];
#pragma unroll
    for (int i = 0; i < 2; i++)
#pragma unroll
        for (int j = 0; j < 8; j++)
#pragma unroll
            for (int q = 0; q < 4; q++) acc[i][j][q] = 0.0f;

    uint4 pa[4];
#pragma unroll
    for (int it = 0; it < 4; it++) {
        int idx = tid + it * 256;
        int row = idx >> 3, q = idx & 7;
        int gm = m0 + row;
        pa[it] = (gm < TT)
            ? *reinterpret_cast<const uint4*>(g_AXH + (size_t)gm * 256 + q * 8)
            : make_uint4(0u, 0u, 0u, 0u);
    }

    for (int kc = 0; kc < 4; kc++) {
#pragma unroll
        for (int it = 0; it < 4; it++) {
            int idx = tid + it * 256;
            int row = idx >> 3, q = idx & 7;
            *reinterpret_cast<uint4*>(&As[row * LDM + q * 4]) = pa[it];
        }
#pragma unroll
        for (int it = 0; it < 4; it++) {
            int idx = tid + it * 256;
            int row = idx >> 3, q = idx & 7;
            uint4 v = *reinterpret_cast<const uint4*>(WT + (size_t)row * 256 + kc * 64 + q * 8);
            *reinterpret_cast<uint4*>(&Bs[row * LDM + q * 4]) = v;
        }
        __syncthreads();
        if (kc < 3) {
#pragma unroll
            for (int it = 0; it < 4; it++) {
                int idx = tid + it * 256;
                int row = idx >> 3, q = idx & 7;
                int gm = m0 + row;
                pa[it] = (gm < TT)
                    ? *reinterpret_cast<const uint4*>(g_AXH + (size_t)gm * 256 + (kc + 1) * 64 + q * 8)
                    : make_uint4(0u, 0u, 0u, 0u);
            }
        }
#pragma unroll
        for (int ks = 0; ks < 4; ks++) {
            int k8 = ks * 8;
            uint32_t a[2][4], b[8][2];
#pragma unroll
            for (int i = 0; i < 2; i++) {
                int m = wm * 32 + i * 16 + row_in;
                a[i][0] = As[m * LDM + k8 + kq];
                a[i][1] = As[(m + 8) * LDM + k8 + kq];
                a[i][2] = As[m * LDM + k8 + kq + 4];
                a[i][3] = As[(m + 8) * LDM + k8 + kq + 4];
            }
#pragma unroll
            for (int j = 0; j < 8; j++) {
                int n = wn * 64 + j * 8 + row_in;
                b[j][0] = Bs[n * LDM + k8 + kq];
                b[j][1] = Bs[n * LDM + k8 + kq + 4];
            }
#pragma unroll
            for (int i = 0; i < 2; i++)
#pragma unroll
                for (int j = 0; j < 8; j++)
                    mma_f16(acc[i][j], a[i], b[j]);
        }
        __syncthreads();
    }

    float* Hst = g_h + (size_t)l * TT * HH;
#pragma unroll
    for (int i = 0; i < 2; i++) {
        int r0 = m0 + wm * 32 + i * 16 + row_in;
#pragma unroll
        for (int half = 0; half < 2; half++) {
            int m = r0 + half * 8;
            if (m >= TT) continue;
#pragma unroll
            for (int j = 0; j < 8; j++) {
                int n = wn * 64 + j * 8 + 2 * kq;
                float v0 = acc[i][j][half * 2 + 0] + bias[n];
                float v1 = acc[i][j][half * 2 + 1] + bias[n + 1];
                size_t o = (size_t)m * HH + n;
                if (MODE == 0) {
                    float s0 = 1.0f / (1.0f + expf(-v0));
                    float s1 = 1.0f / (1.0f + expf(-v1));
                    if (y == 0) {
                        float2 hv = *reinterpret_cast<const float2*>(&Hst[o]);
                        float2 rv; rv.x = s0 * hv.x; rv.y = s1 * hv.y;
                        *reinterpret_cast<float2*>(&g_RH[o]) = rv;
                    } else {
                        float2 uv; uv.x = s0; uv.y = s1;
                        *reinterpret_cast<float2*>(&g_U[o]) = uv;
                    }
                } else {
                    float c0 = tanhf(v0), c1 = tanhf(v1);
                    float2 uv = *reinterpret_cast<const float2*>(&g_U[o]);
                    float2 hv = *reinterpret_cast<const float2*>(&Hst[o]);
                    hv.x = uv.x * hv.x + (1.0f - uv.x) * c0;
                    hv.y = uv.y * hv.y + (1.0f - uv.y) * c1;
                    *reinterpret_cast<float2*>(&Hst[o]) = hv;
                }
            }
        }
    }
}

// ---------------- batchnorm + output -----------------------------------------
__global__ void bn_partial() {
    int j = threadIdx.x;
    int b = blockIdx.x;
    const float* h1 = g_h + (size_t)(LL - 1) * TT * HH;
    float s = 0.0f, q = 0.0f;
    int r0 = b * (TT / 160), r1 = r0 + (TT / 160);
    for (int r = r0; r < r1; r++) {
        float v = h1[(size_t)r * HH + j];
        s += v; q += v * v;
    }
    g_psum[b * HH + j] = s;
    g_psq[b * HH + j]  = q;
}

__global__ void bn_final() {
    int j = threadIdx.x;
    float s = 0.0f, q = 0.0f;
    for (int b = 0; b < 160; b++) { s += g_psum[b * HH + j]; q += g_psq[b * HH + j]; }
    float m = s / (float)TT;
    float var = q / (float)TT - m * m;
    g_mean[j] = m;
    g_rstd[j] = rsqrtf(var + 1e-5f);
}

__global__ void final_kernel(const float* __restrict__ Wout,
                             const float* __restrict__ bout,
                             const float* __restrict__ gamma,
                             const float* __restrict__ beta,
                             float* __restrict__ out) {
    int warp = (blockIdx.x * blockDim.x + threadIdx.x) >> 5;
    int lane = threadIdx.x & 31;
    if (warp >= TT) return;
    const float* h1 = g_h + (size_t)(LL - 1) * TT * HH + (size_t)warp * HH;
    float a0 = 0.f, a1 = 0.f, a2 = 0.f, a3 = 0.f;
    for (int k = lane; k < HH; k += 32) {
        float v = (h1[k] - g_mean[k]) * g_rstd[k] * gamma[k] + beta[k];
        v = fmaxf(v, 0.0f);
        a0 = fmaf(v, Wout[k * 4 + 0], a0);
        a1 = fmaf(v, Wout[k * 4 + 1], a1);
        a2 = fmaf(v, Wout[k * 4 + 2], a2);
        a3 = fmaf(v, Wout[k * 4 + 3], a3);
    }
#pragma unroll
    for (int o = 16; o; o >>= 1) {
        a0 += __shfl_xor_sync(0xFFFFFFFFu, a0, o);
        a1 += __shfl_xor_sync(0xFFFFFFFFu, a1, o);
        a2 += __shfl_xor_sync(0xFFFFFFFFu, a2, o);
        a3 += __shfl_xor_sync(0xFFFFFFFFu, a3, o);
    }
    if (lane == 0) {
        a0 += bout[0]; a1 += bout[1]; a2 += bout[2]; a3 += bout[3];
        float mx = fmaxf(fmaxf(a0, a1), fmaxf(a2, a3));
        float se = expf(a0 - mx) + expf(a1 - mx) + expf(a2 - mx) + expf(a3 - mx);
        float lse = mx + logf(se);
        out[(size_t)warp * 4 + 0] = a0 - lse;
        out[(size_t)warp * 4 + 1] = a1 - lse;
        out[(size_t)warp * 4 + 2] = a2 - lse;
        out[(size_t)warp * 4 + 3] = a3 - lse;
    }
}

// ---------------- host orchestration -----------------------------------------
extern "C" void kernel_launch(void* const* d_in, const int* in_sizes, int n_in,
                              void* d_out, int out_size) {
    const float* x_seq      = (const float*)d_in[0];
    const int*   edge_index = (const int*)  d_in[1];
    const float* edge_weight= (const float*)d_in[2];
    const float* lin_in_W   = (const float*)d_in[3];
    const float* lin_in_b   = (const float*)d_in[4];
    const float* convW      = (const float*)d_in[5];
    const float* convB      = (const float*)d_in[6];
    const float* bn_gamma   = (const float*)d_in[7];
    const float* bn_beta    = (const float*)d_in[8];
    const float* lin_out_W  = (const float*)d_in[9];
    const float* lin_out_b  = (const float*)d_in[10];
    float* out = (float*)d_out;
    (void)in_sizes; (void)n_in; (void)out_size;

    // launches: 1 prep, 2 fused init+linin, 3 spmm_xh, 4 gemm_mma<0> (ncu slot)
    prep_all<<<1, 1024>>>(edge_index, edge_weight);
    init_and_linin<<<MISC_BLOCKS + SS * TT, 128>>>(convW, x_seq, lin_in_W, lin_in_b);

    dim3 gridRU((TT + 127) / 128, 2);
    dim3 gridC ((TT + 127) / 128, 1);

    for (int s = 0; s < SS; s++) {
        for (int l = 0; l < LL; l++) {
            spmm_xh<<<TT, 128>>>(l, s);
            gemm_mma<0><<<gridRU, 256>>>(l, convB);
            spmm_rh<<<TT, 128>>>();
            gemm_mma<1><<<gridC, 256>>>(l, convB);
        }
    }

    bn_partial<<<160, 128>>>();
    bn_final<<<1, 128>>>();
    final_kernel<<<(TT * 32 + 255) / 256, 256>>>(lin_out_W, lin_out_b,
                                                 bn_gamma, bn_beta, out);
}

// round 6
// speedup vs baseline: 3.8420x; 1.1215x over previous
#include <cuda_runtime.h>
#include <cuda_fp16.h>
#include <math.h>
#include <cstdint>

#define NN 5000
#define BB 8
#define TT 40000      // BB*NN
#define EE 40000
#define SS 12
#define FF 16
#define HH 128
#define LL 2
#define NE (EE + NN)  // CSR entries (edges + self loops)

// ---------------- device scratch (static: no allocation allowed) ------------
__device__ float g_deg[NN];
__device__ float g_dis[NN];
__device__ int   g_cnt[NN];
__device__ int   g_ptr[NN + 1];
__device__ int   g_wpos[NN];
__device__ int   g_src[NE];
__device__ float g_wv[NE];
__device__ int   g_key[NE];

__device__ float  g_Xt[(size_t)SS * TT * HH];     // relu(lin_in), all steps, fp32
__device__ float  g_h[(size_t)LL * TT * HH];      // hidden states fp32
__device__ __half g_AXH[(size_t)TT * 2 * HH];     // [Ax | Ah] / [Ax | Arh] fp16
__device__ float  g_RH[(size_t)TT * HH];          // r * h fp32
__device__ float  g_U[(size_t)TT * HH];           // u gate fp32
__device__ __half g_WruT[(size_t)LL * 256 * 256]; // [n][k] fp16: n<128 W_r, n>=128 W_u
__device__ __half g_WcT[(size_t)LL * 128 * 256];  // [n][k] fp16
__device__ float  g_psum[160 * HH];
__device__ float  g_psq[160 * HH];
__device__ float  g_mean[HH];
__device__ float  g_rstd[HH];

// ---------------- cp.async helpers -------------------------------------------
__device__ __forceinline__ uint32_t smem_u32(const void* p) {
    uint32_t a;
    asm("{ .reg .u64 t; cvta.to.shared.u64 t, %1; cvt.u32.u64 %0, t; }"
        : "=r"(a) : "l"(p));
    return a;
}
#define CP_ASYNC16(dst, src) \
    asm volatile("cp.async.cg.shared.global [%0], [%1], 16;" :: "r"(dst), "l"(src))
#define CP_COMMIT() asm volatile("cp.async.commit_group;" ::: "memory")
#define CP_WAIT1()  asm volatile("cp.async.wait_group 1;" ::: "memory")
#define CP_WAIT0()  asm volatile("cp.async.wait_group 0;" ::: "memory")

// ---------------- single-block cooperative graph prep -----------------------
__global__ void prep_all(const int* __restrict__ ei, const float* __restrict__ ew) {
    int tid = threadIdx.x;                       // 1024 threads, 1 block
    for (int i = tid; i < NN; i += 1024) { g_deg[i] = 1.0f; g_cnt[i] = 1; }
    __syncthreads();
    for (int e = tid; e < EE; e += 1024) {
        int c = ei[EE + e];
        atomicAdd(&g_deg[c], ew[e]);
        atomicAdd(&g_cnt[c], 1);
    }
    __syncthreads();
    for (int i = tid; i < NN; i += 1024) g_dis[i] = rsqrtf(g_deg[i]);
    __syncthreads();
    __shared__ int sh[1024];
    __shared__ int carry;
    if (tid == 0) carry = 0;
    __syncthreads();
    for (int base = 0; base < NN; base += 1024) {
        int i = base + tid;
        int v = (i < NN) ? g_cnt[i] : 0;
        sh[tid] = v;
        __syncthreads();
        for (int off = 1; off < 1024; off <<= 1) {
            int t = (tid >= off) ? sh[tid - off] : 0;
            __syncthreads();
            sh[tid] += t;
            __syncthreads();
        }
        int excl = sh[tid] - v + carry;
        if (i < NN) g_ptr[i] = excl;
        __syncthreads();
        if (tid == 1023) carry += sh[1023];
        __syncthreads();
    }
    if (tid == 0) g_ptr[NN] = carry;
    __syncthreads();
    for (int i = tid; i < NN; i += 1024) {
        int p = g_ptr[i];
        g_src[p] = i;
        g_wv[p]  = g_dis[i] * g_dis[i];
        g_key[p] = -1;
        g_wpos[i] = p + 1;
    }
    __syncthreads();
    for (int e = tid; e < EE; e += 1024) {
        int r = ei[e];
        int c = ei[EE + e];
        int p = atomicAdd(&g_wpos[c], 1);
        g_src[p] = r;
        g_wv[p]  = g_dis[r] * ew[e] * g_dis[c];
        g_key[p] = e;
    }
    __syncthreads();
    for (int c = tid; c < NN; c += 1024) {
        int s0 = g_ptr[c] + 1, s1 = g_ptr[c + 1];
        for (int i = s0 + 1; i < s1; i++) {
            int k = g_key[i]; int sr = g_src[i]; float w = g_wv[i];
            int j = i - 1;
            while (j >= s0 && g_key[j] > k) {
                g_key[j + 1] = g_key[j]; g_src[j + 1] = g_src[j]; g_wv[j + 1] = g_wv[j];
                j--;
            }
            g_key[j + 1] = k; g_src[j + 1] = sr; g_wv[j + 1] = w;
        }
    }
}

// --------- fused: weight pack (fp16) + zero h + lin_in (all steps) -----------
#define W1 (LL * 256 * 256)
#define W2 (LL * 128 * 256)
#define W3 (LL * TT * HH)
#define MISC_BLOCKS ((W1 + W2 + W3 + 127) / 128)

__global__ void init_and_linin(const float* __restrict__ convW,
                               const float* __restrict__ x_seq,
                               const float* __restrict__ W,
                               const float* __restrict__ bias) {
    if (blockIdx.x < MISC_BLOCKS) {
        size_t i = (size_t)blockIdx.x * 128 + threadIdx.x;
        if (i < W1) {
            int l = (int)(i >> 16), rem = (int)(i & 65535);
            int n = rem >> 8, k = rem & 255;
            int g = n >> 7, j = n & 127;
            g_WruT[i] = __float2half(convW[((size_t)(l * 3 + g) * 256 + k) * 128 + j]);
        } else if (i < (size_t)W1 + W2) {
            size_t q = i - W1;
            int l = (int)(q >> 15), rem = (int)(q & 32767);
            int n = rem >> 8, k = rem & 255;
            g_WcT[q] = __float2half(convW[((size_t)(l * 3 + 2) * 256 + k) * 128 + n]);
        } else if (i < (size_t)W1 + W2 + W3) {
            g_h[i - W1 - W2] = 0.0f;
        }
    } else {
        int t2 = blockIdx.x - MISC_BLOCKS;   // 0 .. SS*TT-1
        int s = t2 / TT, t = t2 - s * TT;
        int b = t / NN, n = t - b * NN;
        int j = threadIdx.x;                 // 0..127
        __shared__ float xs[FF];
        if (j < FF) xs[j] = x_seq[(((size_t)b * SS + s) * NN + n) * FF + j];
        __syncthreads();
        float acc = bias[j];
#pragma unroll
        for (int k = 0; k < FF; k++) acc = fmaf(xs[k], W[k * HH + j], acc);
        g_Xt[(size_t)s * TT * HH + (size_t)t * HH + j] = fmaxf(acc, 0.0f);
    }
}

// ---------------- SpMM gathers (fp32 in, fp16 out), 32-bit addressing --------
__global__ void __launch_bounds__(128) spmm_xh(int l, int s) {
    int t = blockIdx.x;
    int c = t % NN;
    int base = t - c;
    int j = threadIdx.x;               // 0..127
    const float* X = (l == 0) ? (g_Xt + (size_t)s * TT * HH) : g_h;
    const float* H = g_h + (size_t)l * TT * HH;
    const float* px = X + base * HH + j;
    const float* ph = H + base * HH + j;
    int s0 = g_ptr[c], s1 = g_ptr[c + 1];
    float ax = 0.0f, ah = 0.0f;
    int e = s0;
    for (; e + 4 <= s1; e += 4) {
        int o0 = g_src[e] * HH,     o1 = g_src[e + 1] * HH;
        int o2 = g_src[e + 2] * HH, o3 = g_src[e + 3] * HH;
        float w0 = g_wv[e],     w1 = g_wv[e + 1];
        float w2 = g_wv[e + 2], w3 = g_wv[e + 3];
        float x0 = __ldg(px + o0), x1 = __ldg(px + o1);
        float x2 = __ldg(px + o2), x3 = __ldg(px + o3);
        float h0 = __ldg(ph + o0), h1 = __ldg(ph + o1);
        float h2 = __ldg(ph + o2), h3 = __ldg(ph + o3);
        ax = fmaf(w0, x0, ax); ah = fmaf(w0, h0, ah);
        ax = fmaf(w1, x1, ax); ah = fmaf(w1, h1, ah);
        ax = fmaf(w2, x2, ax); ah = fmaf(w2, h2, ah);
        ax = fmaf(w3, x3, ax); ah = fmaf(w3, h3, ah);
    }
    for (; e < s1; e++) {
        int o = g_src[e] * HH;
        float w = g_wv[e];
        ax = fmaf(w, __ldg(px + o), ax);
        ah = fmaf(w, __ldg(ph + o), ah);
    }
    g_AXH[t * 256 + j] = __float2half(ax);
    g_AXH[t * 256 + 128 + j] = __float2half(ah);
}

__global__ void __launch_bounds__(128) spmm_rh() {
    int t = blockIdx.x;
    int c = t % NN;
    int base = t - c;
    int j = threadIdx.x;               // 0..127
    const float* pr = g_RH + base * HH + j;
    int s0 = g_ptr[c], s1 = g_ptr[c + 1];
    float acc = 0.0f;
    int e = s0;
    for (; e + 4 <= s1; e += 4) {
        int o0 = g_src[e] * HH,     o1 = g_src[e + 1] * HH;
        int o2 = g_src[e + 2] * HH, o3 = g_src[e + 3] * HH;
        float w0 = g_wv[e],     w1 = g_wv[e + 1];
        float w2 = g_wv[e + 2], w3 = g_wv[e + 3];
        float v0 = __ldg(pr + o0), v1 = __ldg(pr + o1);
        float v2 = __ldg(pr + o2), v3 = __ldg(pr + o3);
        acc = fmaf(w0, v0, acc); acc = fmaf(w1, v1, acc);
        acc = fmaf(w2, v2, acc); acc = fmaf(w3, v3, acc);
    }
    for (; e < s1; e++)
        acc = fmaf(g_wv[e], __ldg(pr + g_src[e] * HH), acc);
    g_AXH[t * 256 + 128 + j] = __float2half(acc);
}

// ---------------- fp16 mma.sync GEMM, cp.async double-buffered ---------------
// C[40000 x 128] = AXH[40000 x 256] @ W-half (fp16 operands, fp32 accumulate).
// K = 256 halves in 4 chunks of 64; 2-stage smem pipeline via cp.async.
#define LDM 36
#define CHUNK_U32 (128 * LDM)          // one stage of one operand, in uint32

__device__ __forceinline__ void mma_f16(float* c, const uint32_t* a, const uint32_t* b) {
    asm volatile(
        "mma.sync.aligned.m16n8k16.row.col.f32.f16.f16.f32 "
        "{%0,%1,%2,%3}, {%4,%5,%6,%7}, {%8,%9}, {%0,%1,%2,%3};"
        : "+f"(c[0]), "+f"(c[1]), "+f"(c[2]), "+f"(c[3])
        : "r"(a[0]), "r"(a[1]), "r"(a[2]), "r"(a[3]), "r"(b[0]), "r"(b[1]));
}

template <int MODE>
__global__ void __launch_bounds__(256) gemm_mma(int l, const float* __restrict__ convB) {
    extern __shared__ uint32_t smem[];
    uint32_t* As = smem;                         // [2][CHUNK_U32]
    uint32_t* Bs = smem + 2 * CHUNK_U32;         // [2][CHUNK_U32]

    int tid = threadIdx.x;
    int wid = tid >> 5, lane = tid & 31;
    int row_in = lane >> 2, kq = lane & 3;
    int wm = wid & 3, wn = wid >> 2;             // 4x2 warp grid, warp tile 32x64
    int m0 = blockIdx.x * 128;
    int y  = blockIdx.y;

    const __half* WT  = (MODE == 0) ? (g_WruT + (size_t)l * 256 * 256 + (size_t)y * 128 * 256)
                                    : (g_WcT  + (size_t)l * 128 * 256);
    const float* bias = (MODE == 0) ? (convB + (size_t)l * 3 * HH + (size_t)y * HH)
                                    : (convB + (size_t)(l * 3 + 2) * HH);

    // per-thread copy slots: 4 iterations x (1 A + 1 B) 16B transfers per chunk
    int crow[4], cq[4];
    const __half* asrc[4];
    const __half* bsrc[4];
    uint32_t adst[4], bdst[4];
#pragma unroll
    for (int it = 0; it < 4; it++) {
        int idx = tid + it * 256;                // 0..1023
        int row = idx >> 3, q = idx & 7;
        crow[it] = row; cq[it] = q;
        int gm = m0 + row; if (gm >= TT) gm = TT - 1;   // clamp (outputs guarded)
        asrc[it] = g_AXH + (size_t)gm * 256 + q * 8;
        bsrc[it] = WT + (size_t)row * 256 + q * 8;
        uint32_t off = (uint32_t)(row * LDM + q * 4) * 4u;
        adst[it] = smem_u32(As) + off;
        bdst[it] = smem_u32(Bs) + off;
    }
    const uint32_t stageA = CHUNK_U32 * 4u;      // bytes per stage
    float acc[2][8][4];
#pragma unroll
    for (int i = 0; i < 2; i++)
#pragma unroll
        for (int j = 0; j < 8; j++)
#pragma unroll
            for (int q = 0; q < 4; q++) acc[i][j][q] = 0.0f;

    // prefetch chunk 0 -> stage 0
#pragma unroll
    for (int it = 0; it < 4; it++) {
        CP_ASYNC16(adst[it], asrc[it]);
        CP_ASYNC16(bdst[it], bsrc[it]);
    }
    CP_COMMIT();

    for (int kc = 0; kc < 4; kc++) {
        int st = kc & 1;
        if (kc < 3) {                            // prefetch next chunk
            int nst = (kc + 1) & 1;
#pragma unroll
            for (int it = 0; it < 4; it++) {
                CP_ASYNC16(adst[it] + nst * stageA, asrc[it] + (kc + 1) * 64);
                CP_ASYNC16(bdst[it] + nst * stageA, bsrc[it] + (kc + 1) * 64);
            }
            CP_COMMIT();
            CP_WAIT1();                          // chunk kc landed
        } else {
            CP_WAIT0();
        }
        __syncthreads();

        const uint32_t* Ast = As + st * CHUNK_U32;
        const uint32_t* Bst = Bs + st * CHUNK_U32;
#pragma unroll
        for (int ks = 0; ks < 4; ks++) {
            int k8 = ks * 8;
            uint32_t a[2][4], b[8][2];
#pragma unroll
            for (int i = 0; i < 2; i++) {
                int m = wm * 32 + i * 16 + row_in;
                a[i][0] = Ast[m * LDM + k8 + kq];
                a[i][1] = Ast[(m + 8) * LDM + k8 + kq];
                a[i][2] = Ast[m * LDM + k8 + kq + 4];
                a[i][3] = Ast[(m + 8) * LDM + k8 + kq + 4];
            }
#pragma unroll
            for (int j = 0; j < 8; j++) {
                int n = wn * 64 + j * 8 + row_in;
                b[j][0] = Bst[n * LDM + k8 + kq];
                b[j][1] = Bst[n * LDM + k8 + kq + 4];
            }
#pragma unroll
            for (int i = 0; i < 2; i++)
#pragma unroll
                for (int j = 0; j < 8; j++)
                    mma_f16(acc[i][j], a[i], b[j]);
        }
        __syncthreads();                         // stage free for next prefetch
    }

    float* Hst = g_h + (size_t)l * TT * HH;
#pragma unroll
    for (int i = 0; i < 2; i++) {
        int r0 = m0 + wm * 32 + i * 16 + row_in;
#pragma unroll
        for (int half = 0; half < 2; half++) {
            int m = r0 + half * 8;
            if (m >= TT) continue;
#pragma unroll
            for (int j = 0; j < 8; j++) {
                int n = wn * 64 + j * 8 + 2 * kq;
                float v0 = acc[i][j][half * 2 + 0] + bias[n];
                float v1 = acc[i][j][half * 2 + 1] + bias[n + 1];
                size_t o = (size_t)m * HH + n;
                if (MODE == 0) {
                    float s0 = 1.0f / (1.0f + expf(-v0));
                    float s1 = 1.0f / (1.0f + expf(-v1));
                    if (y == 0) {
                        float2 hv = *reinterpret_cast<const float2*>(&Hst[o]);
                        float2 rv; rv.x = s0 * hv.x; rv.y = s1 * hv.y;
                        *reinterpret_cast<float2*>(&g_RH[o]) = rv;
                    } else {
                        float2 uv; uv.x = s0; uv.y = s1;
                        *reinterpret_cast<float2*>(&g_U[o]) = uv;
                    }
                } else {
                    float c0 = tanhf(v0), c1 = tanhf(v1);
                    float2 uv = *reinterpret_cast<const float2*>(&g_U[o]);
                    float2 hv = *reinterpret_cast<const float2*>(&Hst[o]);
                    hv.x = uv.x * hv.x + (1.0f - uv.x) * c0;
                    hv.y = uv.y * hv.y + (1.0f - uv.y) * c1;
                    *reinterpret_cast<float2*>(&Hst[o]) = hv;
                }
            }
        }
    }
}

// ---------------- batchnorm + output -----------------------------------------
__global__ void bn_partial() {
    int j = threadIdx.x;
    int b = blockIdx.x;
    const float* h1 = g_h + (size_t)(LL - 1) * TT * HH;
    float s = 0.0f, q = 0.0f;
    int r0 = b * (TT / 160), r1 = r0 + (TT / 160);
    for (int r = r0; r < r1; r++) {
        float v = h1[(size_t)r * HH + j];
        s += v; q += v * v;
    }
    g_psum[b * HH + j] = s;
    g_psq[b * HH + j]  = q;
}

__global__ void bn_final() {
    int j = threadIdx.x;
    float s = 0.0f, q = 0.0f;
    for (int b = 0; b < 160; b++) { s += g_psum[b * HH + j]; q += g_psq[b * HH + j]; }
    float m = s / (float)TT;
    float var = q / (float)TT - m * m;
    g_mean[j] = m;
    g_rstd[j] = rsqrtf(var + 1e-5f);
}

__global__ void final_kernel(const float* __restrict__ Wout,
                             const float* __restrict__ bout,
                             const float* __restrict__ gamma,
                             const float* __restrict__ beta,
                             float* __restrict__ out) {
    int warp = (blockIdx.x * blockDim.x + threadIdx.x) >> 5;
    int lane = threadIdx.x & 31;
    if (warp >= TT) return;
    const float* h1 = g_h + (size_t)(LL - 1) * TT * HH + (size_t)warp * HH;
    float a0 = 0.f, a1 = 0.f, a2 = 0.f, a3 = 0.f;
    for (int k = lane; k < HH; k += 32) {
        float v = (h1[k] - g_mean[k]) * g_rstd[k] * gamma[k] + beta[k];
        v = fmaxf(v, 0.0f);
        a0 = fmaf(v, Wout[k * 4 + 0], a0);
        a1 = fmaf(v, Wout[k * 4 + 1], a1);
        a2 = fmaf(v, Wout[k * 4 + 2], a2);
        a3 = fmaf(v, Wout[k * 4 + 3], a3);
    }
#pragma unroll
    for (int o = 16; o; o >>= 1) {
        a0 += __shfl_xor_sync(0xFFFFFFFFu, a0, o);
        a1 += __shfl_xor_sync(0xFFFFFFFFu, a1, o);
        a2 += __shfl_xor_sync(0xFFFFFFFFu, a2, o);
        a3 += __shfl_xor_sync(0xFFFFFFFFu, a3, o);
    }
    if (lane == 0) {
        a0 += bout[0]; a1 += bout[1]; a2 += bout[2]; a3 += bout[3];
        float mx = fmaxf(fmaxf(a0, a1), fmaxf(a2, a3));
        float se = expf(a0 - mx) + expf(a1 - mx) + expf(a2 - mx) + expf(a3 - mx);
        float lse = mx + logf(se);
        out[(size_t)warp * 4 + 0] = a0 - lse;
        out[(size_t)warp * 4 + 1] = a1 - lse;
        out[(size_t)warp * 4 + 2] = a2 - lse;
        out[(size_t)warp * 4 + 3] = a3 - lse;
    }
}

// ---------------- host orchestration -----------------------------------------
extern "C" void kernel_launch(void* const* d_in, const int* in_sizes, int n_in,
                              void* d_out, int out_size) {
    const float* x_seq      = (const float*)d_in[0];
    const int*   edge_index = (const int*)  d_in[1];
    const float* edge_weight= (const float*)d_in[2];
    const float* lin_in_W   = (const float*)d_in[3];
    const float* lin_in_b   = (const float*)d_in[4];
    const float* convW      = (const float*)d_in[5];
    const float* convB      = (const float*)d_in[6];
    const float* bn_gamma   = (const float*)d_in[7];
    const float* bn_beta    = (const float*)d_in[8];
    const float* lin_out_W  = (const float*)d_in[9];
    const float* lin_out_b  = (const float*)d_in[10];
    float* out = (float*)d_out;
    (void)in_sizes; (void)n_in; (void)out_size;

    const int GSMEM = 4 * CHUNK_U32 * 4;   // 73728 bytes
    cudaFuncSetAttribute(gemm_mma<0>, cudaFuncAttributeMaxDynamicSharedMemorySize, GSMEM);
    cudaFuncSetAttribute(gemm_mma<1>, cudaFuncAttributeMaxDynamicSharedMemorySize, GSMEM);

    // launches: 1 prep, 2 fused init+linin, 3 spmm_xh, 4 gemm_mma<0> (ncu slot)
    prep_all<<<1, 1024>>>(edge_index, edge_weight);
    init_and_linin<<<MISC_BLOCKS + SS * TT, 128>>>(convW, x_seq, lin_in_W, lin_in_b);

    dim3 gridRU((TT + 127) / 128, 2);
    dim3 gridC ((TT + 127) / 128, 1);

    for (int s = 0; s < SS; s++) {
        for (int l = 0; l < LL; l++) {
            spmm_xh<<<TT, 128>>>(l, s);
            gemm_mma<0><<<gridRU, 256, GSMEM>>>(l, convB);
            spmm_rh<<<TT, 128>>>();
            gemm_mma<1><<<gridC, 256, GSMEM>>>(l, convB);
        }
    }

    bn_partial<<<160, 128>>>();
    bn_final<<<1, 128>>>();
    final_kernel<<<(TT * 32 + 255) / 256, 256>>>(lin_out_W, lin_out_b,
                                                 bn_gamma, bn_beta, out);
}

// round 7
// speedup vs baseline: 4.1586x; 1.0824x over previous
#include <cuda_runtime.h>
#include <cuda_fp16.h>
#include <math.h>
#include <cstdint>

#define NN 5000
#define BB 8
#define TT 40000      // BB*NN
#define EE 40000
#define SS 12
#define FF 16
#define HH 128
#define LL 2
#define NE (EE + NN)  // CSR entries (edges + self loops)

// ---------------- device scratch (static: no allocation allowed) ------------
__device__ float g_deg[NN];
__device__ float g_dis[NN];
__device__ int   g_cnt[NN];
__device__ int   g_ptr[NN + 1];
__device__ int   g_wpos[NN];
__device__ int   g_src[NE];
__device__ float g_wv[NE];
__device__ int   g_key[NE];

__device__ float  g_Xt[(size_t)SS * TT * HH];     // relu(lin_in), all steps, fp32
__device__ float  g_h[(size_t)LL * TT * HH];      // hidden states fp32
__device__ __half g_AXH[(size_t)TT * 2 * HH];     // [Ax | Ah] / [Ax | Arh] fp16
__device__ float  g_RH[(size_t)TT * HH];          // r * h fp32
__device__ float  g_U[(size_t)TT * HH];           // u gate fp32
__device__ __half g_WruT[(size_t)LL * 256 * 256]; // [n][k] fp16: n<128 W_r, n>=128 W_u
__device__ __half g_WcT[(size_t)LL * 128 * 256];  // [n][k] fp16
__device__ float  g_psum[160 * HH];
__device__ float  g_psq[160 * HH];
__device__ float  g_mean[HH];
__device__ float  g_rstd[HH];

// ---------------- cp.async helpers -------------------------------------------
__device__ __forceinline__ uint32_t smem_u32(const void* p) {
    uint32_t a;
    asm("{ .reg .u64 t; cvta.to.shared.u64 t, %1; cvt.u32.u64 %0, t; }"
        : "=r"(a) : "l"(p));
    return a;
}
#define CP_ASYNC16(dst, src) \
    asm volatile("cp.async.cg.shared.global [%0], [%1], 16;" :: "r"(dst), "l"(src))
#define CP_COMMIT() asm volatile("cp.async.commit_group;" ::: "memory")
#define CP_WAIT2()  asm volatile("cp.async.wait_group 2;" ::: "memory")
#define CP_WAIT1()  asm volatile("cp.async.wait_group 1;" ::: "memory")
#define CP_WAIT0()  asm volatile("cp.async.wait_group 0;" ::: "memory")

// ---------------- single-block cooperative graph prep -----------------------
__global__ void prep_all(const int* __restrict__ ei, const float* __restrict__ ew) {
    int tid = threadIdx.x;                       // 1024 threads, 1 block
    for (int i = tid; i < NN; i += 1024) { g_deg[i] = 1.0f; g_cnt[i] = 1; }
    __syncthreads();
    for (int e = tid; e < EE; e += 1024) {
        int c = ei[EE + e];
        atomicAdd(&g_deg[c], ew[e]);
        atomicAdd(&g_cnt[c], 1);
    }
    __syncthreads();
    for (int i = tid; i < NN; i += 1024) g_dis[i] = rsqrtf(g_deg[i]);
    __syncthreads();
    __shared__ int sh[1024];
    __shared__ int carry;
    if (tid == 0) carry = 0;
    __syncthreads();
    for (int base = 0; base < NN; base += 1024) {
        int i = base + tid;
        int v = (i < NN) ? g_cnt[i] : 0;
        sh[tid] = v;
        __syncthreads();
        for (int off = 1; off < 1024; off <<= 1) {
            int t = (tid >= off) ? sh[tid - off] : 0;
            __syncthreads();
            sh[tid] += t;
            __syncthreads();
        }
        int excl = sh[tid] - v + carry;
        if (i < NN) g_ptr[i] = excl;
        __syncthreads();
        if (tid == 1023) carry += sh[1023];
        __syncthreads();
    }
    if (tid == 0) g_ptr[NN] = carry;
    __syncthreads();
    for (int i = tid; i < NN; i += 1024) {
        int p = g_ptr[i];
        g_src[p] = i;
        g_wv[p]  = g_dis[i] * g_dis[i];
        g_key[p] = -1;
        g_wpos[i] = p + 1;
    }
    __syncthreads();
    for (int e = tid; e < EE; e += 1024) {
        int r = ei[e];
        int c = ei[EE + e];
        int p = atomicAdd(&g_wpos[c], 1);
        g_src[p] = r;
        g_wv[p]  = g_dis[r] * ew[e] * g_dis[c];
        g_key[p] = e;
    }
    __syncthreads();
    for (int c = tid; c < NN; c += 1024) {
        int s0 = g_ptr[c] + 1, s1 = g_ptr[c + 1];
        for (int i = s0 + 1; i < s1; i++) {
            int k = g_key[i]; int sr = g_src[i]; float w = g_wv[i];
            int j = i - 1;
            while (j >= s0 && g_key[j] > k) {
                g_key[j + 1] = g_key[j]; g_src[j + 1] = g_src[j]; g_wv[j + 1] = g_wv[j];
                j--;
            }
            g_key[j + 1] = k; g_src[j + 1] = sr; g_wv[j + 1] = w;
        }
    }
}

// --------- fused: weight pack (fp16) + zero h + lin_in (all steps) -----------
#define W1 (LL * 256 * 256)
#define W2 (LL * 128 * 256)
#define W3 (LL * TT * HH)
#define MISC_BLOCKS ((W1 + W2 + W3 + 127) / 128)

__global__ void init_and_linin(const float* __restrict__ convW,
                               const float* __restrict__ x_seq,
                               const float* __restrict__ W,
                               const float* __restrict__ bias) {
    if (blockIdx.x < MISC_BLOCKS) {
        size_t i = (size_t)blockIdx.x * 128 + threadIdx.x;
        if (i < W1) {
            int l = (int)(i >> 16), rem = (int)(i & 65535);
            int n = rem >> 8, k = rem & 255;
            int g = n >> 7, j = n & 127;
            g_WruT[i] = __float2half(convW[((size_t)(l * 3 + g) * 256 + k) * 128 + j]);
        } else if (i < (size_t)W1 + W2) {
            size_t q = i - W1;
            int l = (int)(q >> 15), rem = (int)(q & 32767);
            int n = rem >> 8, k = rem & 255;
            g_WcT[q] = __float2half(convW[((size_t)(l * 3 + 2) * 256 + k) * 128 + n]);
        } else if (i < (size_t)W1 + W2 + W3) {
            g_h[i - W1 - W2] = 0.0f;
        }
    } else {
        int t2 = blockIdx.x - MISC_BLOCKS;   // 0 .. SS*TT-1
        int s = t2 / TT, t = t2 - s * TT;
        int b = t / NN, n = t - b * NN;
        int j = threadIdx.x;                 // 0..127
        __shared__ float xs[FF];
        if (j < FF) xs[j] = x_seq[(((size_t)b * SS + s) * NN + n) * FF + j];
        __syncthreads();
        float acc = bias[j];
#pragma unroll
        for (int k = 0; k < FF; k++) acc = fmaf(xs[k], W[k * HH + j], acc);
        g_Xt[(size_t)s * TT * HH + (size_t)t * HH + j] = fmaxf(acc, 0.0f);
    }
}

// ---------------- SpMM gathers, float2 per thread ----------------------------
// 128 threads: warps 0-1 gather x (cols 2*j2, 2*j2+1), warps 2-3 gather h.
__global__ void __launch_bounds__(128) spmm_xh(int l, int s) {
    int t = blockIdx.x;
    int c = t % NN;
    int base = t - c;
    int tid = threadIdx.x;
    int j2 = tid & 63;                 // float2 column pair
    bool isH = tid >= 64;
    const float* X = (l == 0) ? (g_Xt + (size_t)s * TT * HH) : g_h;
    const float* H = g_h + (size_t)l * TT * HH;
    const float2* p = reinterpret_cast<const float2*>(isH ? H : X) + base * 64 + j2;
    int s0 = g_ptr[c], s1 = g_ptr[c + 1];
    float ax = 0.0f, ay = 0.0f;
    int e = s0;
    for (; e + 4 <= s1; e += 4) {
        int o0 = g_src[e] * 64,     o1 = g_src[e + 1] * 64;
        int o2 = g_src[e + 2] * 64, o3 = g_src[e + 3] * 64;
        float w0 = g_wv[e],     w1 = g_wv[e + 1];
        float w2 = g_wv[e + 2], w3 = g_wv[e + 3];
        float2 v0 = __ldg(p + o0), v1 = __ldg(p + o1);
        float2 v2 = __ldg(p + o2), v3 = __ldg(p + o3);
        ax = fmaf(w0, v0.x, ax); ay = fmaf(w0, v0.y, ay);
        ax = fmaf(w1, v1.x, ax); ay = fmaf(w1, v1.y, ay);
        ax = fmaf(w2, v2.x, ax); ay = fmaf(w2, v2.y, ay);
        ax = fmaf(w3, v3.x, ax); ay = fmaf(w3, v3.y, ay);
    }
    for (; e < s1; e++) {
        float w = g_wv[e];
        float2 v = __ldg(p + g_src[e] * 64);
        ax = fmaf(w, v.x, ax); ay = fmaf(w, v.y, ay);
    }
    __half2* outp = reinterpret_cast<__half2*>(g_AXH) + t * 128 + (isH ? 64 : 0) + j2;
    *outp = __floats2half2_rn(ax, ay);
}

// AXH[:, 128:256] = Ahat @ (r*h) ; 64 threads, float2
__global__ void __launch_bounds__(64) spmm_rh() {
    int t = blockIdx.x;
    int c = t % NN;
    int base = t - c;
    int j2 = threadIdx.x;              // 0..63
    const float2* p = reinterpret_cast<const float2*>(g_RH) + base * 64 + j2;
    int s0 = g_ptr[c], s1 = g_ptr[c + 1];
    float ax = 0.0f, ay = 0.0f;
    int e = s0;
    for (; e + 4 <= s1; e += 4) {
        int o0 = g_src[e] * 64,     o1 = g_src[e + 1] * 64;
        int o2 = g_src[e + 2] * 64, o3 = g_src[e + 3] * 64;
        float w0 = g_wv[e],     w1 = g_wv[e + 1];
        float w2 = g_wv[e + 2], w3 = g_wv[e + 3];
        float2 v0 = __ldg(p + o0), v1 = __ldg(p + o1);
        float2 v2 = __ldg(p + o2), v3 = __ldg(p + o3);
        ax = fmaf(w0, v0.x, ax); ay = fmaf(w0, v0.y, ay);
        ax = fmaf(w1, v1.x, ax); ay = fmaf(w1, v1.y, ay);
        ax = fmaf(w2, v2.x, ax); ay = fmaf(w2, v2.y, ay);
        ax = fmaf(w3, v3.x, ax); ay = fmaf(w3, v3.y, ay);
    }
    for (; e < s1; e++) {
        float w = g_wv[e];
        float2 v = __ldg(p + g_src[e] * 64);
        ax = fmaf(w, v.x, ax); ay = fmaf(w, v.y, ay);
    }
    __half2* outp = reinterpret_cast<__half2*>(g_AXH) + t * 128 + 64 + j2;
    *outp = __floats2half2_rn(ax, ay);
}

// ---------------- fp16 mma.sync GEMM, 4-stage cp.async, chunk K=32 -----------
// C[40000 x 128] = AXH[40000 x 256] @ W-half. 8 chunks of 32 halves.
#define LDM2 20                         // u32 per row per chunk (16 data + 4 pad)
#define STG_U32 (128 * LDM2)            // 2560 u32 = 10240 B per operand-stage
#define STG_B   (STG_U32 * 4)

__device__ __forceinline__ void mma_f16(float* c, const uint32_t* a, const uint32_t* b) {
    asm volatile(
        "mma.sync.aligned.m16n8k16.row.col.f32.f16.f16.f32 "
        "{%0,%1,%2,%3}, {%4,%5,%6,%7}, {%8,%9}, {%0,%1,%2,%3};"
        : "+f"(c[0]), "+f"(c[1]), "+f"(c[2]), "+f"(c[3])
        : "r"(a[0]), "r"(a[1]), "r"(a[2]), "r"(a[3]), "r"(b[0]), "r"(b[1]));
}

template <int MODE>
__global__ void __launch_bounds__(256, 2) gemm_mma(int l, const float* __restrict__ convB) {
    extern __shared__ uint32_t smem[];
    uint32_t* As = smem;                 // [4][STG_U32]
    uint32_t* Bs = smem + 4 * STG_U32;   // [4][STG_U32]

    int tid = threadIdx.x;
    int wid = tid >> 5, lane = tid & 31;
    int row_in = lane >> 2, kq = lane & 3;
    int wm = wid & 3, wn = wid >> 2;     // 4x2 warp grid, warp tile 32x64
    int m0 = blockIdx.x * 128;
    int y  = blockIdx.y;

    const __half* WT  = (MODE == 0) ? (g_WruT + (size_t)l * 256 * 256 + (size_t)y * 128 * 256)
                                    : (g_WcT  + (size_t)l * 128 * 256);
    const float* bias = (MODE == 0) ? (convB + (size_t)l * 3 * HH + (size_t)y * HH)
                                    : (convB + (size_t)(l * 3 + 2) * HH);

    // per-thread copy slots: 2 iterations x (1 A + 1 B) 16B transfers per chunk
    const __half* asrc[2];
    const __half* bsrc[2];
    uint32_t adst[2], bdst[2];
#pragma unroll
    for (int it = 0; it < 2; it++) {
        int idx = tid + it * 256;        // 0..511
        int row = idx >> 2, q = idx & 3; // row 0..127, q slot (16B = 8 halves)
        int gm = m0 + row; if (gm >= TT) gm = TT - 1;   // clamp (outputs guarded)
        asrc[it] = g_AXH + (size_t)gm * 256 + q * 8;
        bsrc[it] = WT + (size_t)row * 256 + q * 8;
        uint32_t off = (uint32_t)(row * LDM2 + q * 4) * 4u;
        adst[it] = smem_u32(As) + off;
        bdst[it] = smem_u32(Bs) + off;
    }

    float acc[2][8][4];
#pragma unroll
    for (int i = 0; i < 2; i++)
#pragma unroll
        for (int j = 0; j < 8; j++)
#pragma unroll
            for (int q = 0; q < 4; q++) acc[i][j][q] = 0.0f;

    // prologue: chunks 0..2 into stages 0..2
#pragma unroll
    for (int pc = 0; pc < 3; pc++) {
#pragma unroll
        for (int it = 0; it < 2; it++) {
            CP_ASYNC16(adst[it] + pc * STG_B, asrc[it] + pc * 32);
            CP_ASYNC16(bdst[it] + pc * STG_B, bsrc[it] + pc * 32);
        }
        CP_COMMIT();
    }

#pragma unroll
    for (int kc = 0; kc < 8; kc++) {
        if (kc < 6) CP_WAIT2();
        else if (kc == 6) CP_WAIT1();
        else CP_WAIT0();
        __syncthreads();
        if (kc + 3 < 8) {
            int nst = (kc + 3) & 3;
#pragma unroll
            for (int it = 0; it < 2; it++) {
                CP_ASYNC16(adst[it] + nst * STG_B, asrc[it] + (kc + 3) * 32);
                CP_ASYNC16(bdst[it] + nst * STG_B, bsrc[it] + (kc + 3) * 32);
            }
            CP_COMMIT();
        }
        const uint32_t* Ast = As + (kc & 3) * STG_U32;
        const uint32_t* Bst = Bs + (kc & 3) * STG_U32;
#pragma unroll
        for (int ks = 0; ks < 2; ks++) {
            int k8 = ks * 8;
            uint32_t a[2][4], b[8][2];
#pragma unroll
            for (int i = 0; i < 2; i++) {
                int m = wm * 32 + i * 16 + row_in;
                a[i][0] = Ast[m * LDM2 + k8 + kq];
                a[i][1] = Ast[(m + 8) * LDM2 + k8 + kq];
                a[i][2] = Ast[m * LDM2 + k8 + kq + 4];
                a[i][3] = Ast[(m + 8) * LDM2 + k8 + kq + 4];
            }
#pragma unroll
            for (int j = 0; j < 8; j++) {
                int n = wn * 64 + j * 8 + row_in;
                b[j][0] = Bst[n * LDM2 + k8 + kq];
                b[j][1] = Bst[n * LDM2 + k8 + kq + 4];
            }
#pragma unroll
            for (int i = 0; i < 2; i++)
#pragma unroll
                for (int j = 0; j < 8; j++)
                    mma_f16(acc[i][j], a[i], b[j]);
        }
    }

    float* Hst = g_h + (size_t)l * TT * HH;
#pragma unroll
    for (int i = 0; i < 2; i++) {
        int r0 = m0 + wm * 32 + i * 16 + row_in;
#pragma unroll
        for (int half = 0; half < 2; half++) {
            int m = r0 + half * 8;
            if (m >= TT) continue;
#pragma unroll
            for (int j = 0; j < 8; j++) {
                int n = wn * 64 + j * 8 + 2 * kq;
                float v0 = acc[i][j][half * 2 + 0] + bias[n];
                float v1 = acc[i][j][half * 2 + 1] + bias[n + 1];
                size_t o = (size_t)m * HH + n;
                if (MODE == 0) {
                    float s0 = 1.0f / (1.0f + expf(-v0));
                    float s1 = 1.0f / (1.0f + expf(-v1));
                    if (y == 0) {
                        float2 hv = *reinterpret_cast<const float2*>(&Hst[o]);
                        float2 rv; rv.x = s0 * hv.x; rv.y = s1 * hv.y;
                        *reinterpret_cast<float2*>(&g_RH[o]) = rv;
                    } else {
                        float2 uv; uv.x = s0; uv.y = s1;
                        *reinterpret_cast<float2*>(&g_U[o]) = uv;
                    }
                } else {
                    float c0 = tanhf(v0), c1 = tanhf(v1);
                    float2 uv = *reinterpret_cast<const float2*>(&g_U[o]);
                    float2 hv = *reinterpret_cast<const float2*>(&Hst[o]);
                    hv.x = uv.x * hv.x + (1.0f - uv.x) * c0;
                    hv.y = uv.y * hv.y + (1.0f - uv.y) * c1;
                    *reinterpret_cast<float2*>(&Hst[o]) = hv;
                }
            }
        }
    }
}

// ---------------- batchnorm + output -----------------------------------------
__global__ void bn_partial() {
    int j = threadIdx.x;
    int b = blockIdx.x;
    const float* h1 = g_h + (size_t)(LL - 1) * TT * HH;
    float s = 0.0f, q = 0.0f;
    int r0 = b * (TT / 160), r1 = r0 + (TT / 160);
    for (int r = r0; r < r1; r++) {
        float v = h1[(size_t)r * HH + j];
        s += v; q += v * v;
    }
    g_psum[b * HH + j] = s;
    g_psq[b * HH + j]  = q;
}

__global__ void bn_final() {
    int j = threadIdx.x;
    float s = 0.0f, q = 0.0f;
    for (int b = 0; b < 160; b++) { s += g_psum[b * HH + j]; q += g_psq[b * HH + j]; }
    float m = s / (float)TT;
    float var = q / (float)TT - m * m;
    g_mean[j] = m;
    g_rstd[j] = rsqrtf(var + 1e-5f);
}

__global__ void final_kernel(const float* __restrict__ Wout,
                             const float* __restrict__ bout,
                             const float* __restrict__ gamma,
                             const float* __restrict__ beta,
                             float* __restrict__ out) {
    int warp = (blockIdx.x * blockDim.x + threadIdx.x) >> 5;
    int lane = threadIdx.x & 31;
    if (warp >= TT) return;
    const float* h1 = g_h + (size_t)(LL - 1) * TT * HH + (size_t)warp * HH;
    float a0 = 0.f, a1 = 0.f, a2 = 0.f, a3 = 0.f;
    for (int k = lane; k < HH; k += 32) {
        float v = (h1[k] - g_mean[k]) * g_rstd[k] * gamma[k] + beta[k];
        v = fmaxf(v, 0.0f);
        a0 = fmaf(v, Wout[k * 4 + 0], a0);
        a1 = fmaf(v, Wout[k * 4 + 1], a1);
        a2 = fmaf(v, Wout[k * 4 + 2], a2);
        a3 = fmaf(v, Wout[k * 4 + 3], a3);
    }
#pragma unroll
    for (int o = 16; o; o >>= 1) {
        a0 += __shfl_xor_sync(0xFFFFFFFFu, a0, o);
        a1 += __shfl_xor_sync(0xFFFFFFFFu, a1, o);
        a2 += __shfl_xor_sync(0xFFFFFFFFu, a2, o);
        a3 += __shfl_xor_sync(0xFFFFFFFFu, a3, o);
    }
    if (lane == 0) {
        a0 += bout[0]; a1 += bout[1]; a2 += bout[2]; a3 += bout[3];
        float mx = fmaxf(fmaxf(a0, a1), fmaxf(a2, a3));
        float se = expf(a0 - mx) + expf(a1 - mx) + expf(a2 - mx) + expf(a3 - mx);
        float lse = mx + logf(se);
        out[(size_t)warp * 4 + 0] = a0 - lse;
        out[(size_t)warp * 4 + 1] = a1 - lse;
        out[(size_t)warp * 4 + 2] = a2 - lse;
        out[(size_t)warp * 4 + 3] = a3 - lse;
    }
}

// ---------------- host orchestration -----------------------------------------
extern "C" void kernel_launch(void* const* d_in, const int* in_sizes, int n_in,
                              void* d_out, int out_size) {
    const float* x_seq      = (const float*)d_in[0];
    const int*   edge_index = (const int*)  d_in[1];
    const float* edge_weight= (const float*)d_in[2];
    const float* lin_in_W   = (const float*)d_in[3];
    const float* lin_in_b   = (const float*)d_in[4];
    const float* convW      = (const float*)d_in[5];
    const float* convB      = (const float*)d_in[6];
    const float* bn_gamma   = (const float*)d_in[7];
    const float* bn_beta    = (const float*)d_in[8];
    const float* lin_out_W  = (const float*)d_in[9];
    const float* lin_out_b  = (const float*)d_in[10];
    float* out = (float*)d_out;
    (void)in_sizes; (void)n_in; (void)out_size;

    const int GSMEM = 8 * STG_U32 * 4;   // 81920 bytes (4 stages x 2 operands)
    cudaFuncSetAttribute(gemm_mma<0>, cudaFuncAttributeMaxDynamicSharedMemorySize, GSMEM);
    cudaFuncSetAttribute(gemm_mma<1>, cudaFuncAttributeMaxDynamicSharedMemorySize, GSMEM);

    // launches: 1 prep, 2 fused init+linin, 3 spmm_xh, 4 gemm_mma<0> (ncu slot)
    prep_all<<<1, 1024>>>(edge_index, edge_weight);
    init_and_linin<<<MISC_BLOCKS + SS * TT, 128>>>(convW, x_seq, lin_in_W, lin_in_b);

    dim3 gridRU((TT + 127) / 128, 2);
    dim3 gridC ((TT + 127) / 128, 1);

    for (int s = 0; s < SS; s++) {
        for (int l = 0; l < LL; l++) {
            spmm_xh<<<TT, 128>>>(l, s);
            gemm_mma<0><<<gridRU, 256, GSMEM>>>(l, convB);
            spmm_rh<<<TT, 64>>>();
            gemm_mma<1><<<gridC, 256, GSMEM>>>(l, convB);
        }
    }

    bn_partial<<<160, 128>>>();
    bn_final<<<1, 128>>>();
    final_kernel<<<(TT * 32 + 255) / 256, 256>>>(lin_out_W, lin_out_b,
                                                 bn_gamma, bn_beta, out);
}

// round 8
// speedup vs baseline: 4.3624x; 1.0490x over previous
#include <cuda_runtime.h>
#include <cuda_fp16.h>
#include <math.h>
#include <cstdint>

#define NN 5000
#define BB 8
#define TT 40000      // BB*NN
#define EE 40000
#define SS 12
#define FF 16
#define HH 128
#define LL 2
#define NE (EE + NN)  // CSR entries (edges + self loops)

// ---------------- device scratch (static: no allocation allowed) ------------
__device__ float g_deg[NN];
__device__ float g_dis[NN];
__device__ int   g_cnt[NN];
__device__ int   g_ptr[NN + 1];
__device__ int   g_wpos[NN];
__device__ int   g_src[NE];
__device__ float g_wv[NE];
__device__ int   g_key[NE];

__device__ __half g_Xt[(size_t)SS * TT * HH];     // relu(lin_in), all steps, fp16
__device__ float  g_h[(size_t)LL * TT * HH];      // hidden states fp32 (master)
__device__ __half g_hf[(size_t)LL * TT * HH];     // fp16 copy of h (gather source)
__device__ __half g_AXH[(size_t)TT * 2 * HH];     // [Ax | Ah] / [Ax | Arh] fp16
__device__ __half g_RH[(size_t)TT * HH];          // r * h fp16 (gather source)
__device__ float  g_U[(size_t)TT * HH];           // u gate fp32
__device__ __half g_WruT[(size_t)LL * 256 * 256]; // [n][k] fp16: n<128 W_r, n>=128 W_u
__device__ __half g_WcT[(size_t)LL * 128 * 256];  // [n][k] fp16
__device__ float  g_psum[160 * HH];
__device__ float  g_psq[160 * HH];
__device__ float  g_mean[HH];
__device__ float  g_rstd[HH];

// ---------------- cp.async helpers -------------------------------------------
__device__ __forceinline__ uint32_t smem_u32(const void* p) {
    uint32_t a;
    asm("{ .reg .u64 t; cvta.to.shared.u64 t, %1; cvt.u32.u64 %0, t; }"
        : "=r"(a) : "l"(p));
    return a;
}
#define CP_ASYNC16(dst, src) \
    asm volatile("cp.async.cg.shared.global [%0], [%1], 16;" :: "r"(dst), "l"(src))
#define CP_COMMIT() asm volatile("cp.async.commit_group;" ::: "memory")
#define CP_WAIT2()  asm volatile("cp.async.wait_group 2;" ::: "memory")
#define CP_WAIT1()  asm volatile("cp.async.wait_group 1;" ::: "memory")
#define CP_WAIT0()  asm volatile("cp.async.wait_group 0;" ::: "memory")

// ---------------- single-block cooperative graph prep -----------------------
__global__ void prep_all(const int* __restrict__ ei, const float* __restrict__ ew) {
    int tid = threadIdx.x;                       // 1024 threads, 1 block
    for (int i = tid; i < NN; i += 1024) { g_deg[i] = 1.0f; g_cnt[i] = 1; }
    __syncthreads();
    for (int e = tid; e < EE; e += 1024) {
        int c = ei[EE + e];
        atomicAdd(&g_deg[c], ew[e]);
        atomicAdd(&g_cnt[c], 1);
    }
    __syncthreads();
    for (int i = tid; i < NN; i += 1024) g_dis[i] = rsqrtf(g_deg[i]);
    __syncthreads();
    __shared__ int sh[1024];
    __shared__ int carry;
    if (tid == 0) carry = 0;
    __syncthreads();
    for (int base = 0; base < NN; base += 1024) {
        int i = base + tid;
        int v = (i < NN) ? g_cnt[i] : 0;
        sh[tid] = v;
        __syncthreads();
        for (int off = 1; off < 1024; off <<= 1) {
            int t = (tid >= off) ? sh[tid - off] : 0;
            __syncthreads();
            sh[tid] += t;
            __syncthreads();
        }
        int excl = sh[tid] - v + carry;
        if (i < NN) g_ptr[i] = excl;
        __syncthreads();
        if (tid == 1023) carry += sh[1023];
        __syncthreads();
    }
    if (tid == 0) g_ptr[NN] = carry;
    __syncthreads();
    for (int i = tid; i < NN; i += 1024) {
        int p = g_ptr[i];
        g_src[p] = i;
        g_wv[p]  = g_dis[i] * g_dis[i];
        g_key[p] = -1;
        g_wpos[i] = p + 1;
    }
    __syncthreads();
    for (int e = tid; e < EE; e += 1024) {
        int r = ei[e];
        int c = ei[EE + e];
        int p = atomicAdd(&g_wpos[c], 1);
        g_src[p] = r;
        g_wv[p]  = g_dis[r] * ew[e] * g_dis[c];
        g_key[p] = e;
    }
    __syncthreads();
    for (int c = tid; c < NN; c += 1024) {
        int s0 = g_ptr[c] + 1, s1 = g_ptr[c + 1];
        for (int i = s0 + 1; i < s1; i++) {
            int k = g_key[i]; int sr = g_src[i]; float w = g_wv[i];
            int j = i - 1;
            while (j >= s0 && g_key[j] > k) {
                g_key[j + 1] = g_key[j]; g_src[j + 1] = g_src[j]; g_wv[j + 1] = g_wv[j];
                j--;
            }
            g_key[j + 1] = k; g_src[j + 1] = sr; g_wv[j + 1] = w;
        }
    }
}

// --- fused: weight pack (fp16) + zero h (fp32 + fp16) + lin_in (all steps) ---
#define W1 (LL * 256 * 256)
#define W2 (LL * 128 * 256)
#define W3 (LL * TT * HH)
#define MISC_BLOCKS ((W1 + W2 + 2 * W3 + 127) / 128)

__global__ void init_and_linin(const float* __restrict__ convW,
                               const float* __restrict__ x_seq,
                               const float* __restrict__ W,
                               const float* __restrict__ bias) {
    if (blockIdx.x < MISC_BLOCKS) {
        size_t i = (size_t)blockIdx.x * 128 + threadIdx.x;
        if (i < W1) {
            int l = (int)(i >> 16), rem = (int)(i & 65535);
            int n = rem >> 8, k = rem & 255;
            int g = n >> 7, j = n & 127;
            g_WruT[i] = __float2half(convW[((size_t)(l * 3 + g) * 256 + k) * 128 + j]);
        } else if (i < (size_t)W1 + W2) {
            size_t q = i - W1;
            int l = (int)(q >> 15), rem = (int)(q & 32767);
            int n = rem >> 8, k = rem & 255;
            g_WcT[q] = __float2half(convW[((size_t)(l * 3 + 2) * 256 + k) * 128 + n]);
        } else if (i < (size_t)W1 + W2 + W3) {
            g_h[i - W1 - W2] = 0.0f;
        } else if (i < (size_t)W1 + W2 + 2 * W3) {
            g_hf[i - W1 - W2 - W3] = __float2half(0.0f);
        }
    } else {
        int t2 = blockIdx.x - MISC_BLOCKS;   // 0 .. SS*TT-1
        int s = t2 / TT, t = t2 - s * TT;
        int b = t / NN, n = t - b * NN;
        int j = threadIdx.x;                 // 0..127
        __shared__ float xs[FF];
        if (j < FF) xs[j] = x_seq[(((size_t)b * SS + s) * NN + n) * FF + j];
        __syncthreads();
        float acc = bias[j];
#pragma unroll
        for (int k = 0; k < FF; k++) acc = fmaf(xs[k], W[k * HH + j], acc);
        g_Xt[(size_t)s * TT * HH + (size_t)t * HH + j] = __float2half(fmaxf(acc, 0.0f));
    }
}

// ---------------- SpMM gathers (fp16 sources, fp32 accumulate) ---------------
// 2 nodes / block. tid>>6 = node-sub, (tid>>5)&1 = {x,h}, lane*4 = column group.
__global__ void __launch_bounds__(128) spmm_xh(int l, int s) {
    int tid = threadIdx.x;
    int t = blockIdx.x * 2 + (tid >> 6);
    int sub = (tid >> 5) & 1;
    int lane = tid & 31;
    int c = t % NN;
    int base = t - c;
    const __half* xsrc = (l == 0) ? (g_Xt + (size_t)s * TT * HH) : g_hf;
    const __half* S = sub ? (g_hf + (size_t)l * TT * HH) : xsrc;
    const uint2* p = reinterpret_cast<const uint2*>(S) + base * 32 + lane;
    int s0 = g_ptr[c], s1 = g_ptr[c + 1];
    float a0 = 0.f, a1 = 0.f, a2 = 0.f, a3 = 0.f;
    int e = s0;
    for (; e + 2 <= s1; e += 2) {
        int o0 = g_src[e] * 32, o1 = g_src[e + 1] * 32;
        float w0 = g_wv[e], w1 = g_wv[e + 1];
        uint2 v0 = __ldg(p + o0), v1 = __ldg(p + o1);
        float2 p00 = __half22float2(*reinterpret_cast<__half2*>(&v0.x));
        float2 p01 = __half22float2(*reinterpret_cast<__half2*>(&v0.y));
        float2 p10 = __half22float2(*reinterpret_cast<__half2*>(&v1.x));
        float2 p11 = __half22float2(*reinterpret_cast<__half2*>(&v1.y));
        a0 = fmaf(w0, p00.x, a0); a1 = fmaf(w0, p00.y, a1);
        a2 = fmaf(w0, p01.x, a2); a3 = fmaf(w0, p01.y, a3);
        a0 = fmaf(w1, p10.x, a0); a1 = fmaf(w1, p10.y, a1);
        a2 = fmaf(w1, p11.x, a2); a3 = fmaf(w1, p11.y, a3);
    }
    for (; e < s1; e++) {
        float w = g_wv[e];
        uint2 v = __ldg(p + g_src[e] * 32);
        float2 q0 = __half22float2(*reinterpret_cast<__half2*>(&v.x));
        float2 q1 = __half22float2(*reinterpret_cast<__half2*>(&v.y));
        a0 = fmaf(w, q0.x, a0); a1 = fmaf(w, q0.y, a1);
        a2 = fmaf(w, q1.x, a2); a3 = fmaf(w, q1.y, a3);
    }
    uint2 o;
    __half2 h0 = __floats2half2_rn(a0, a1);
    __half2 h1 = __floats2half2_rn(a2, a3);
    o.x = *reinterpret_cast<uint32_t*>(&h0);
    o.y = *reinterpret_cast<uint32_t*>(&h1);
    *(reinterpret_cast<uint2*>(g_AXH + t * 256 + sub * 128) + lane) = o;
}

// AXH[:, 128:256] = Ahat @ (r*h) ; 4 nodes / block
__global__ void __launch_bounds__(128) spmm_rh() {
    int tid = threadIdx.x;
    int t = blockIdx.x * 4 + (tid >> 5);
    int lane = tid & 31;
    int c = t % NN;
    int base = t - c;
    const uint2* p = reinterpret_cast<const uint2*>(g_RH) + base * 32 + lane;
    int s0 = g_ptr[c], s1 = g_ptr[c + 1];
    float a0 = 0.f, a1 = 0.f, a2 = 0.f, a3 = 0.f;
    int e = s0;
    for (; e + 2 <= s1; e += 2) {
        int o0 = g_src[e] * 32, o1 = g_src[e + 1] * 32;
        float w0 = g_wv[e], w1 = g_wv[e + 1];
        uint2 v0 = __ldg(p + o0), v1 = __ldg(p + o1);
        float2 p00 = __half22float2(*reinterpret_cast<__half2*>(&v0.x));
        float2 p01 = __half22float2(*reinterpret_cast<__half2*>(&v0.y));
        float2 p10 = __half22float2(*reinterpret_cast<__half2*>(&v1.x));
        float2 p11 = __half22float2(*reinterpret_cast<__half2*>(&v1.y));
        a0 = fmaf(w0, p00.x, a0); a1 = fmaf(w0, p00.y, a1);
        a2 = fmaf(w0, p01.x, a2); a3 = fmaf(w0, p01.y, a3);
        a0 = fmaf(w1, p10.x, a0); a1 = fmaf(w1, p10.y, a1);
        a2 = fmaf(w1, p11.x, a2); a3 = fmaf(w1, p11.y, a3);
    }
    for (; e < s1; e++) {
        float w = g_wv[e];
        uint2 v = __ldg(p + g_src[e] * 32);
        float2 q0 = __half22float2(*reinterpret_cast<__half2*>(&v.x));
        float2 q1 = __half22float2(*reinterpret_cast<__half2*>(&v.y));
        a0 = fmaf(w, q0.x, a0); a1 = fmaf(w, q0.y, a1);
        a2 = fmaf(w, q1.x, a2); a3 = fmaf(w, q1.y, a3);
    }
    uint2 o;
    __half2 h0 = __floats2half2_rn(a0, a1);
    __half2 h1 = __floats2half2_rn(a2, a3);
    o.x = *reinterpret_cast<uint32_t*>(&h0);
    o.y = *reinterpret_cast<uint32_t*>(&h1);
    *(reinterpret_cast<uint2*>(g_AXH + t * 256 + 128) + lane) = o;
}

// ---------------- fp16 mma.sync GEMMs, 4-stage cp.async, chunk K=32 ----------
#define LDM2 20                         // u32 per row per chunk (16 data + 4 pad)
#define ASTG_U32 (128 * LDM2)           // A stage: 2560 u32
#define ASTG_B   (ASTG_U32 * 4)

__device__ __forceinline__ void mma_f16(float* c, const uint32_t* a, const uint32_t* b) {
    asm volatile(
        "mma.sync.aligned.m16n8k16.row.col.f32.f16.f16.f32 "
        "{%0,%1,%2,%3}, {%4,%5,%6,%7}, {%8,%9}, {%0,%1,%2,%3};"
        : "+f"(c[0]), "+f"(c[1]), "+f"(c[2]), "+f"(c[3])
        : "r"(a[0]), "r"(a[1]), "r"(a[2]), "r"(a[3]), "r"(b[0]), "r"(b[1]));
}

// -------- fused r|u GEMM: 512 threads, tile 128x256, warp grid 4x4 -----------
#define B0STG_U32 (256 * LDM2)          // 5120 u32
#define B0STG_B   (B0STG_U32 * 4)

__global__ void __launch_bounds__(512, 1) gemm_ru(int l, const float* __restrict__ convB) {
    extern __shared__ uint32_t smem[];
    uint32_t* As = smem;                    // [4][ASTG_U32]
    uint32_t* Bs = smem + 4 * ASTG_U32;     // [4][B0STG_U32]

    int tid = threadIdx.x;
    int wid = tid >> 5, lane = tid & 31;
    int row_in = lane >> 2, kq = lane & 3;
    int wm = wid & 3, wn = wid >> 2;        // 4x4 warp grid, warp tile 32x64
    int m0 = blockIdx.x * 128;

    const __half* WT  = g_WruT + (size_t)l * 256 * 256;
    const float* bias = convB + (size_t)l * 3 * HH;   // r cols 0..127, u cols 128..255

    // copy slots: A 1/thread, B 2/thread
    const __half* asrc;
    uint32_t adst;
    {
        int row = tid >> 2, q = tid & 3;
        int gm = m0 + row; if (gm >= TT) gm = TT - 1;
        asrc = g_AXH + (size_t)gm * 256 + q * 8;
        adst = smem_u32(As) + (uint32_t)(row * LDM2 + q * 4) * 4u;
    }
    const __half* bsrc[2];
    uint32_t bdst[2];
#pragma unroll
    for (int it = 0; it < 2; it++) {
        int idx = tid + it * 512;           // 0..1023
        int row = idx >> 2, q = idx & 3;    // row 0..255
        bsrc[it] = WT + (size_t)row * 256 + q * 8;
        bdst[it] = smem_u32(Bs) + (uint32_t)(row * LDM2 + q * 4) * 4u;
    }

    float acc[2][8][4];
#pragma unroll
    for (int i = 0; i < 2; i++)
#pragma unroll
        for (int j = 0; j < 8; j++)
#pragma unroll
            for (int q = 0; q < 4; q++) acc[i][j][q] = 0.0f;

#pragma unroll
    for (int pc = 0; pc < 3; pc++) {
        CP_ASYNC16(adst + pc * ASTG_B, asrc + pc * 32);
#pragma unroll
        for (int it = 0; it < 2; it++)
            CP_ASYNC16(bdst[it] + pc * B0STG_B, bsrc[it] + pc * 32);
        CP_COMMIT();
    }

#pragma unroll
    for (int kc = 0; kc < 8; kc++) {
        if (kc < 6) CP_WAIT2();
        else if (kc == 6) CP_WAIT1();
        else CP_WAIT0();
        __syncthreads();
        if (kc + 3 < 8) {
            int nst = (kc + 3) & 3;
            CP_ASYNC16(adst + nst * ASTG_B, asrc + (kc + 3) * 32);
#pragma unroll
            for (int it = 0; it < 2; it++)
                CP_ASYNC16(bdst[it] + nst * B0STG_B, bsrc[it] + (kc + 3) * 32);
            CP_COMMIT();
        }
        const uint32_t* Ast = As + (kc & 3) * ASTG_U32;
        const uint32_t* Bst = Bs + (kc & 3) * B0STG_U32;
#pragma unroll
        for (int ks = 0; ks < 2; ks++) {
            int k8 = ks * 8;
            uint32_t a[2][4], b[8][2];
#pragma unroll
            for (int i = 0; i < 2; i++) {
                int m = wm * 32 + i * 16 + row_in;
                a[i][0] = Ast[m * LDM2 + k8 + kq];
                a[i][1] = Ast[(m + 8) * LDM2 + k8 + kq];
                a[i][2] = Ast[m * LDM2 + k8 + kq + 4];
                a[i][3] = Ast[(m + 8) * LDM2 + k8 + kq + 4];
            }
#pragma unroll
            for (int j = 0; j < 8; j++) {
                int n = wn * 64 + j * 8 + row_in;
                b[j][0] = Bst[n * LDM2 + k8 + kq];
                b[j][1] = Bst[n * LDM2 + k8 + kq + 4];
            }
#pragma unroll
            for (int i = 0; i < 2; i++)
#pragma unroll
                for (int j = 0; j < 8; j++)
                    mma_f16(acc[i][j], a[i], b[j]);
        }
    }

    const float* Hst = g_h + (size_t)l * TT * HH;
#pragma unroll
    for (int i = 0; i < 2; i++) {
        int r0 = m0 + wm * 32 + i * 16 + row_in;
#pragma unroll
        for (int half = 0; half < 2; half++) {
            int m = r0 + half * 8;
            if (m >= TT) continue;
#pragma unroll
            for (int j = 0; j < 8; j++) {
                int n = wn * 64 + j * 8 + 2 * kq;     // 0..255
                float v0 = acc[i][j][half * 2 + 0] + bias[n];
                float v1 = acc[i][j][half * 2 + 1] + bias[n + 1];
                float s0 = 1.0f / (1.0f + expf(-v0));
                float s1 = 1.0f / (1.0f + expf(-v1));
                if (n < 128) {
                    size_t o = (size_t)m * HH + n;
                    float2 hv = *reinterpret_cast<const float2*>(&Hst[o]);
                    __half2 rv = __floats2half2_rn(s0 * hv.x, s1 * hv.y);
                    *reinterpret_cast<__half2*>(&g_RH[o]) = rv;
                } else {
                    size_t o = (size_t)m * HH + (n - 128);
                    float2 uv; uv.x = s0; uv.y = s1;
                    *reinterpret_cast<float2*>(&g_U[o]) = uv;
                }
            }
        }
    }
}

// -------- candidate GEMM: 256 threads, tile 128x128 --------------------------
__global__ void __launch_bounds__(256, 2) gemm_c(int l, const float* __restrict__ convB) {
    extern __shared__ uint32_t smem[];
    uint32_t* As = smem;                 // [4][ASTG_U32]
    uint32_t* Bs = smem + 4 * ASTG_U32;  // [4][ASTG_U32]

    int tid = threadIdx.x;
    int wid = tid >> 5, lane = tid & 31;
    int row_in = lane >> 2, kq = lane & 3;
    int wm = wid & 3, wn = wid >> 2;     // 4x2 warp grid
    int m0 = blockIdx.x * 128;

    const __half* WT  = g_WcT + (size_t)l * 128 * 256;
    const float* bias = convB + (size_t)(l * 3 + 2) * HH;

    const __half* asrc[2];
    const __half* bsrc[2];
    uint32_t adst[2], bdst[2];
#pragma unroll
    for (int it = 0; it < 2; it++) {
        int idx = tid + it * 256;
        int row = idx >> 2, q = idx & 3;
        int gm = m0 + row; if (gm >= TT) gm = TT - 1;
        asrc[it] = g_AXH + (size_t)gm * 256 + q * 8;
        bsrc[it] = WT + (size_t)row * 256 + q * 8;
        uint32_t off = (uint32_t)(row * LDM2 + q * 4) * 4u;
        adst[it] = smem_u32(As) + off;
        bdst[it] = smem_u32(Bs) + off;
    }

    float acc[2][8][4];
#pragma unroll
    for (int i = 0; i < 2; i++)
#pragma unroll
        for (int j = 0; j < 8; j++)
#pragma unroll
            for (int q = 0; q < 4; q++) acc[i][j][q] = 0.0f;

#pragma unroll
    for (int pc = 0; pc < 3; pc++) {
#pragma unroll
        for (int it = 0; it < 2; it++) {
            CP_ASYNC16(adst[it] + pc * ASTG_B, asrc[it] + pc * 32);
            CP_ASYNC16(bdst[it] + pc * ASTG_B, bsrc[it] + pc * 32);
        }
        CP_COMMIT();
    }

#pragma unroll
    for (int kc = 0; kc < 8; kc++) {
        if (kc < 6) CP_WAIT2();
        else if (kc == 6) CP_WAIT1();
        else CP_WAIT0();
        __syncthreads();
        if (kc + 3 < 8) {
            int nst = (kc + 3) & 3;
#pragma unroll
            for (int it = 0; it < 2; it++) {
                CP_ASYNC16(adst[it] + nst * ASTG_B, asrc[it] + (kc + 3) * 32);
                CP_ASYNC16(bdst[it] + nst * ASTG_B, bsrc[it] + (kc + 3) * 32);
            }
            CP_COMMIT();
        }
        const uint32_t* Ast = As + (kc & 3) * ASTG_U32;
        const uint32_t* Bst = Bs + (kc & 3) * ASTG_U32;
#pragma unroll
        for (int ks = 0; ks < 2; ks++) {
            int k8 = ks * 8;
            uint32_t a[2][4], b[8][2];
#pragma unroll
            for (int i = 0; i < 2; i++) {
                int m = wm * 32 + i * 16 + row_in;
                a[i][0] = Ast[m * LDM2 + k8 + kq];
                a[i][1] = Ast[(m + 8) * LDM2 + k8 + kq];
                a[i][2] = Ast[m * LDM2 + k8 + kq + 4];
                a[i][3] = Ast[(m + 8) * LDM2 + k8 + kq + 4];
            }
#pragma unroll
            for (int j = 0; j < 8; j++) {
                int n = wn * 64 + j * 8 + row_in;
                b[j][0] = Bst[n * LDM2 + k8 + kq];
                b[j][1] = Bst[n * LDM2 + k8 + kq + 4];
            }
#pragma unroll
            for (int i = 0; i < 2; i++)
#pragma unroll
                for (int j = 0; j < 8; j++)
                    mma_f16(acc[i][j], a[i], b[j]);
        }
    }

    float* Hst = g_h + (size_t)l * TT * HH;
    __half* Hf = g_hf + (size_t)l * TT * HH;
#pragma unroll
    for (int i = 0; i < 2; i++) {
        int r0 = m0 + wm * 32 + i * 16 + row_in;
#pragma unroll
        for (int half = 0; half < 2; half++) {
            int m = r0 + half * 8;
            if (m >= TT) continue;
#pragma unroll
            for (int j = 0; j < 8; j++) {
                int n = wn * 64 + j * 8 + 2 * kq;
                float v0 = acc[i][j][half * 2 + 0] + bias[n];
                float v1 = acc[i][j][half * 2 + 1] + bias[n + 1];
                float c0 = tanhf(v0), c1 = tanhf(v1);
                size_t o = (size_t)m * HH + n;
                float2 uv = *reinterpret_cast<const float2*>(&g_U[o]);
                float2 hv = *reinterpret_cast<const float2*>(&Hst[o]);
                hv.x = uv.x * hv.x + (1.0f - uv.x) * c0;
                hv.y = uv.y * hv.y + (1.0f - uv.y) * c1;
                *reinterpret_cast<float2*>(&Hst[o]) = hv;
                *reinterpret_cast<__half2*>(&Hf[o]) = __floats2half2_rn(hv.x, hv.y);
            }
        }
    }
}

// ---------------- batchnorm + output -----------------------------------------
__global__ void bn_partial() {
    int j = threadIdx.x;
    int b = blockIdx.x;
    const float* h1 = g_h + (size_t)(LL - 1) * TT * HH;
    float s = 0.0f, q = 0.0f;
    int r0 = b * (TT / 160), r1 = r0 + (TT / 160);
    for (int r = r0; r < r1; r++) {
        float v = h1[(size_t)r * HH + j];
        s += v; q += v * v;
    }
    g_psum[b * HH + j] = s;
    g_psq[b * HH + j]  = q;
}

__global__ void bn_final() {
    int j = threadIdx.x;
    float s = 0.0f, q = 0.0f;
    for (int b = 0; b < 160; b++) { s += g_psum[b * HH + j]; q += g_psq[b * HH + j]; }
    float m = s / (float)TT;
    float var = q / (float)TT - m * m;
    g_mean[j] = m;
    g_rstd[j] = rsqrtf(var + 1e-5f);
}

__global__ void final_kernel(const float* __restrict__ Wout,
                             const float* __restrict__ bout,
                             const float* __restrict__ gamma,
                             const float* __restrict__ beta,
                             float* __restrict__ out) {
    int warp = (blockIdx.x * blockDim.x + threadIdx.x) >> 5;
    int lane = threadIdx.x & 31;
    if (warp >= TT) return;
    const float* h1 = g_h + (size_t)(LL - 1) * TT * HH + (size_t)warp * HH;
    float a0 = 0.f, a1 = 0.f, a2 = 0.f, a3 = 0.f;
    for (int k = lane; k < HH; k += 32) {
        float v = (h1[k] - g_mean[k]) * g_rstd[k] * gamma[k] + beta[k];
        v = fmaxf(v, 0.0f);
        a0 = fmaf(v, Wout[k * 4 + 0], a0);
        a1 = fmaf(v, Wout[k * 4 + 1], a1);
        a2 = fmaf(v, Wout[k * 4 + 2], a2);
        a3 = fmaf(v, Wout[k * 4 + 3], a3);
    }
#pragma unroll
    for (int o = 16; o; o >>= 1) {
        a0 += __shfl_xor_sync(0xFFFFFFFFu, a0, o);
        a1 += __shfl_xor_sync(0xFFFFFFFFu, a1, o);
        a2 += __shfl_xor_sync(0xFFFFFFFFu, a2, o);
        a3 += __shfl_xor_sync(0xFFFFFFFFu, a3, o);
    }
    if (lane == 0) {
        a0 += bout[0]; a1 += bout[1]; a2 += bout[2]; a3 += bout[3];
        float mx = fmaxf(fmaxf(a0, a1), fmaxf(a2, a3));
        float se = expf(a0 - mx) + expf(a1 - mx) + expf(a2 - mx) + expf(a3 - mx);
        float lse = mx + logf(se);
        out[(size_t)warp * 4 + 0] = a0 - lse;
        out[(size_t)warp * 4 + 1] = a1 - lse;
        out[(size_t)warp * 4 + 2] = a2 - lse;
        out[(size_t)warp * 4 + 3] = a3 - lse;
    }
}

// ---------------- host orchestration -----------------------------------------
extern "C" void kernel_launch(void* const* d_in, const int* in_sizes, int n_in,
                              void* d_out, int out_size) {
    const float* x_seq      = (const float*)d_in[0];
    const int*   edge_index = (const int*)  d_in[1];
    const float* edge_weight= (const float*)d_in[2];
    const float* lin_in_W   = (const float*)d_in[3];
    const float* lin_in_b   = (const float*)d_in[4];
    const float* convW      = (const float*)d_in[5];
    const float* convB      = (const float*)d_in[6];
    const float* bn_gamma   = (const float*)d_in[7];
    const float* bn_beta    = (const float*)d_in[8];
    const float* lin_out_W  = (const float*)d_in[9];
    const float* lin_out_b  = (const float*)d_in[10];
    float* out = (float*)d_out;
    (void)in_sizes; (void)n_in; (void)out_size;

    const int GSMEM_RU = 4 * (ASTG_U32 + B0STG_U32) * 4;   // 122880 B
    const int GSMEM_C  = 8 * ASTG_U32 * 4;                 // 81920 B
    cudaFuncSetAttribute(gemm_ru, cudaFuncAttributeMaxDynamicSharedMemorySize, GSMEM_RU);
    cudaFuncSetAttribute(gemm_c,  cudaFuncAttributeMaxDynamicSharedMemorySize, GSMEM_C);

    // launches: 1 prep, 2 init+linin, 3 spmm_xh, 4 gemm_ru (ncu slot)
    prep_all<<<1, 1024>>>(edge_index, edge_weight);
    init_and_linin<<<MISC_BLOCKS + SS * TT, 128>>>(convW, x_seq, lin_in_W, lin_in_b);

    int gemm_grid = (TT + 127) / 128;   // 313

    for (int s = 0; s < SS; s++) {
        for (int l = 0; l < LL; l++) {
            spmm_xh<<<TT / 2, 128>>>(l, s);
            gemm_ru<<<gemm_grid, 512, GSMEM_RU>>>(l, convB);
            spmm_rh<<<TT / 4, 128>>>();
            gemm_c<<<gemm_grid, 256, GSMEM_C>>>(l, convB);
        }
    }

    bn_partial<<<160, 128>>>();
    bn_final<<<1, 128>>>();
    final_kernel<<<(TT * 32 + 255) / 256, 256>>>(lin_out_W, lin_out_b,
                                                 bn_gamma, bn_beta, out);
}